// round 10
// baseline (speedup 1.0000x reference)
#include <cuda_runtime.h>
#include <cuda_fp16.h>
#include <math.h>
#include <stdint.h>

#define B_    8
#define D_    512
#define L_    1024
#define NPOS  8192
#define KCB   8192
#define EDIM  512
#define SEMD  256
#define NQ    4194304

typedef unsigned long long ull;

// ---------------- scratch ----------------
static __device__ float g_Zn [NPOS * EDIM];
static __device__ char  g_ZnQ[NPOS * EDIM];
static __device__ float g_En [KCB * EDIM];
static __device__ char  g_EnQ[KCB * EDIM];
static __device__ float g_psum[8][NPOS];
static __device__ float g_pmax[8][NPOS];
static __device__ float g_invk[NPOS], g_invg[NPOS];
static __device__ float g_akd[NPOS],  g_agan[NPOS];
static __device__ float g_bkd[KCB],   g_bgan[KCB];
static __device__ float g_a[NPOS], g_b[KCB];         // summed halves
static __device__ float g_sZ[NPOS], g_sE[KCB];       // int8 dequant steps
static __device__ __half g_Dh[(size_t)NPOS * KCB];   // approx dsum fp16, [n][k]
static __device__ unsigned g_keyu[NPOS];
static __device__ int   g_idx[NPOS];
// S-identity scratch
static __device__ float g_G[4 * 65536];              // Grams: E_kd, E_gan, Z_kd, Z_gan
static __device__ float g_vec[2048];                 // s1[512] s2[512] w0[512] w1[512]

// ---------------- helpers ----------------
__device__ __forceinline__ float wsum(float s) {
#pragma unroll
    for (int o = 16; o > 0; o >>= 1) s += __shfl_xor_sync(0xffffffffu, s, o);
    return s;
}
__device__ __forceinline__ float wmax(float s) {
#pragma unroll
    for (int o = 16; o > 0; o >>= 1) s = fmaxf(s, __shfl_xor_sync(0xffffffffu, s, o));
    return s;
}
__device__ __forceinline__ unsigned s2u(const void* p) {
    unsigned a;
    asm("{ .reg .u64 t; cvta.to.shared.u64 t, %1; cvt.u32.u64 %0, t; }" : "=r"(a) : "l"(p));
    return a;
}
__device__ __forceinline__ void cpasync16(unsigned s, const void* g) {
    asm volatile("cp.async.cg.shared.global [%0], [%1], 16;\n" :: "r"(s), "l"(g));
}
__device__ __forceinline__ void ldsm4(unsigned addr, unsigned &r0, unsigned &r1,
                                      unsigned &r2, unsigned &r3) {
    asm volatile("ldmatrix.sync.aligned.m8n8.x4.shared.b16 {%0,%1,%2,%3}, [%4];"
                 : "=r"(r0), "=r"(r1), "=r"(r2), "=r"(r3) : "r"(addr));
}
__device__ __forceinline__ void mma_s8(int* c, unsigned a0, unsigned a1, unsigned a2,
                                       unsigned a3, unsigned b0, unsigned b1) {
    asm volatile("mma.sync.aligned.m16n8k32.row.col.s32.s8.s8.s32 "
                 "{%0,%1,%2,%3}, {%4,%5,%6,%7}, {%8,%9}, {%0,%1,%2,%3};"
                 : "+r"(c[0]), "+r"(c[1]), "+r"(c[2]), "+r"(c[3])
                 : "r"(a0), "r"(a1), "r"(a2), "r"(a3), "r"(b0), "r"(b1));
}

// ---------------- 1. prep: emb normalize+quant | z sumsq+max ----------------
__global__ void k_prep(const float* __restrict__ z, const float* __restrict__ ekd,
                       const float* __restrict__ egan) {
    int bid = blockIdx.x;
    if (bid < 1024) {
        int w = threadIdx.x >> 5, lane = threadIdx.x & 31;
        int k = bid * 8 + w;
        const float* pk = ekd + (size_t)k * SEMD;
        const float* pg = egan + (size_t)k * SEMD;
        float v[8], u[8]; float sk = 0.f, sg = 0.f;
#pragma unroll
        for (int j = 0; j < 8; ++j) {
            v[j] = pk[lane + j * 32]; sk += v[j] * v[j];
            u[j] = pg[lane + j * 32]; sg += u[j] * u[j];
        }
        sk = wsum(sk); sg = wsum(sg);
        float ik = 1.f / fmaxf(sqrtf(sk), 1e-12f);
        float ig = 1.f / fmaxf(sqrtf(sg), 1e-12f);
        float m = 0.f, tk = 0.f, tg = 0.f;
#pragma unroll
        for (int j = 0; j < 8; ++j) {
            v[j] *= ik; u[j] *= ig;
            m = fmaxf(m, fmaxf(fabsf(v[j]), fabsf(u[j])));
            tk += v[j] * v[j]; tg += u[j] * u[j];
        }
        m = wmax(m); tk = wsum(tk); tg = wsum(tg);
        float qs = 127.f / fmaxf(m, 1e-20f);
#pragma unroll
        for (int j = 0; j < 8; ++j) {
            size_t o = (size_t)k * EDIM + lane + j * 32;
            g_En[o] = v[j];          g_EnQ[o] = (char)__float2int_rn(v[j] * qs);
            g_En[o + SEMD] = u[j];   g_EnQ[o + SEMD] = (char)__float2int_rn(u[j] * qs);
        }
        if (lane == 0) {
            g_bkd[k] = tk; g_bgan[k] = tg;
            g_b[k] = tk + tg;
            g_sE[k] = m * (1.f / 127.f);
        }
    } else {
        int i = bid - 1024;
        int l = (i & 3) * 256 + threadIdx.x;
        int b = (i >> 2) & 7, seg = i >> 5;
        const float* p = z + (size_t)b * D_ * L_ + (size_t)seg * 64 * L_ + l;
        float s = 0.f, m = 0.f;
#pragma unroll 8
        for (int d = 0; d < 64; ++d) {
            float v = p[(size_t)d * L_];
            s += v * v; m = fmaxf(m, fabsf(v));
        }
        g_psum[seg][b * L_ + l] = s;
        g_pmax[seg][b * L_ + l] = m;
    }
}

// ---------------- 2. finalize norms/scales + zero S scratch ----------------
__global__ void k_zfinal() {
    int n = blockIdx.x * 256 + threadIdx.x;
    float s = g_psum[0][n] + g_psum[1][n] + g_psum[2][n] + g_psum[3][n];
    float inv = 1.f / fmaxf(sqrtf(s), 1e-12f);
    g_invk[n] = inv;
    float akd = s * inv * inv; g_akd[n] = akd;
    float mk = fmaxf(fmaxf(g_pmax[0][n], g_pmax[1][n]), fmaxf(g_pmax[2][n], g_pmax[3][n])) * inv;
    float s2 = g_psum[4][n] + g_psum[5][n] + g_psum[6][n] + g_psum[7][n];
    float inv2 = 1.f / fmaxf(sqrtf(s2), 1e-12f);
    g_invg[n] = inv2;
    float agan = s2 * inv2 * inv2; g_agan[n] = agan;
    float mg = fmaxf(fmaxf(g_pmax[4][n], g_pmax[5][n]), fmaxf(g_pmax[6][n], g_pmax[7][n])) * inv2;
    g_a[n] = akd + agan;
    g_sZ[n] = fmaxf(mk, mg) * (1.f / 127.f);
    g_keyu[n] = 0xFFFFFFFFu;
    int base = n * 32;
#pragma unroll
    for (int i = 0; i < 32; ++i) g_G[base + i] = 0.f;
    if (n < 2048) g_vec[n] = 0.f;
}

// ---------------- 3. transpose + normalize + quantize z ----------------
__global__ void k_ztrans(const float* __restrict__ z) {
    __shared__ float s[32][33];
    int d0 = blockIdx.x * 32, l0 = blockIdx.y * 32, b = blockIdx.z;
    int tx = threadIdx.x, ty = threadIdx.y;
#pragma unroll
    for (int q = 0; q < 4; ++q) {
        int dy = ty * 4 + q;
        s[dy][tx] = z[((size_t)b * D_ + d0 + dy) * L_ + l0 + tx];
    }
    __syncthreads();
    bool kdh = (d0 < SEMD);
#pragma unroll
    for (int q = 0; q < 4; ++q) {
        int lr = ty * 4 + q;
        int n = b * L_ + l0 + lr;
        float inv = kdh ? g_invk[n] : g_invg[n];
        float v = s[tx][lr] * inv;
        float rq = 1.f / g_sZ[n];
        size_t o = (size_t)n * EDIM + d0 + tx;
        g_Zn[o] = v;
        g_ZnQ[o] = (char)__float2int_rn(v * rq);
    }
}

// ---------------- 4. int8 mma GEMM 128x128, warp 32x64, 4-stage, 2 CTAs/SM ----------------
#define STG4 20480
__global__ void __launch_bounds__(256, 2) k_gemm_mma() {
    extern __shared__ char dsm[];

    const int tid = threadIdx.x, lane = tid & 31, w = tid >> 5;
    const int bid = blockIdx.x;
    const int sup = bid >> 8, loc = bid & 255;
    const int kt = ((sup & 3) << 4) | (loc & 15);
    const int rt = ((sup >> 2) << 4) | (loc >> 4);
    const int row0 = rt * 128, k0 = kt * 128;
    const int wm = w & 3, wn = w >> 2;

    unsigned sbase = s2u(dsm);

    auto load_chunk = [&](int c) {
        int st = c & 3;
        int e0 = c * 64;
        const char* Ag = g_ZnQ + (size_t)row0 * EDIM + e0;
        const char* Bg = g_EnQ + (size_t)k0 * EDIM + e0;
        unsigned ab = sbase + st * STG4;
        unsigned bb = ab + 10240;
#pragma unroll
        for (int i = 0; i < 2; ++i) {
            int q = tid + i * 256; int r = q >> 2, ch = q & 3;
            cpasync16(ab + r * 80 + ch * 16, Ag + (size_t)r * EDIM + ch * 16);
        }
#pragma unroll
        for (int i = 0; i < 2; ++i) {
            int q = tid + i * 256; int r = q >> 2, ch = q & 3;
            cpasync16(bb + r * 80 + ch * 16, Bg + (size_t)r * EDIM + ch * 16);
        }
        asm volatile("cp.async.commit_group;" ::: "memory");
    };

    int acc[2][8][4];
#pragma unroll
    for (int t = 0; t < 2; ++t)
#pragma unroll
        for (int j = 0; j < 8; ++j)
#pragma unroll
            for (int q = 0; q < 4; ++q) acc[t][j][q] = 0;

    const int lr = lane & 7, lg = lane >> 3;

    auto compute = [&](int st) {
        unsigned ab = sbase + st * STG4;
        unsigned bb = ab + 10240;
#pragma unroll
        for (int s = 0; s < 2; ++s) {
            unsigned a0[2], a1[2], a2[2], a3[2];
#pragma unroll
            for (int t = 0; t < 2; ++t) {
                int row = wm * 32 + t * 16 + lr + 8 * (lg & 1);
                int col = s * 16 + 8 * (lg >> 1);
                ldsm4(ab + row * 80 + col * 2, a0[t], a1[t], a2[t], a3[t]);
            }
            unsigned bf[8][2];
#pragma unroll
            for (int jp = 0; jp < 4; ++jp) {
                int brow = wn * 64 + (jp * 2 + (lg >> 1)) * 8 + lr;
                int bcol = s * 16 + 8 * (lg & 1);
                ldsm4(bb + brow * 80 + bcol * 2,
                      bf[jp * 2][0], bf[jp * 2][1], bf[jp * 2 + 1][0], bf[jp * 2 + 1][1]);
            }
#pragma unroll
            for (int t = 0; t < 2; ++t)
#pragma unroll
                for (int j = 0; j < 8; ++j)
                    mma_s8(acc[t][j], a0[t], a1[t], a2[t], a3[t], bf[j][0], bf[j][1]);
        }
    };

    load_chunk(0); load_chunk(1); load_chunk(2);
#pragma unroll 1
    for (int c = 0; c < 8; ++c) {
        asm volatile("cp.async.wait_group 2;" ::: "memory");
        __syncthreads();
        if (c + 3 < 8) load_chunk(c + 3);
        compute(c & 3);
    }

    // ---- epilogue ----
    const int lq = lane >> 2, lp = lane & 3;
    const int kb = k0 + wn * 64 + lp * 2;
#pragma unroll
    for (int t = 0; t < 2; ++t) {
        int rA = row0 + wm * 32 + t * 16 + lq;
#pragma unroll
        for (int h = 0; h < 2; ++h) {
            int rr = rA + 8 * h;
            float a_ = g_a[rr];
            float tz = 2.f * g_sZ[rr];
            unsigned rmin = 0xFFFFFFFFu;
            __half* drow = g_Dh + (size_t)rr * KCB;
#pragma unroll
            for (int j = 0; j < 8; ++j) {
                int kk = kb + j * 8;
                float d0 = (a_ + g_b[kk])     - tz * g_sE[kk]     * (float)acc[t][j][2 * h];
                float d1 = (a_ + g_b[kk + 1]) - tz * g_sE[kk + 1] * (float)acc[t][j][2 * h + 1];
                rmin = min(rmin, min(__float_as_uint(d0), __float_as_uint(d1)));
                *(__half2*)(drow + kk) = __floats2half2_rn(d0, d1);
            }
            rmin = min(rmin, __shfl_xor_sync(0xffffffffu, rmin, 1));
            rmin = min(rmin, __shfl_xor_sync(0xffffffffu, rmin, 2));
            if (lp == 0) atomicMin(&g_keyu[rr], rmin);
        }
    }
}

// ---------------- 5. column sums: s1/s2 (E), w0/w1 (Z) ----------------
__global__ void k_colsum() {
    int bx = blockIdx.x;
    int job = bx >> 5;                 // 0 = E, 1 = Z
    int colg = (bx >> 3) & 3, rsp = bx & 7;
    int col = colg * 128 + (threadIdx.x & 127);
    int sub = threadIdx.x >> 7;
    int r0 = rsp * 1024 + sub * 512;
    const float* M = job ? g_Zn : g_En;
    const float* beta = (col < 256) ? (job ? g_akd : g_bkd) : (job ? g_agan : g_bgan);
    float s1a = 0.f, s2a = 0.f;
    for (int r = r0; r < r0 + 512; ++r) {
        float x = M[(size_t)r * EDIM + col];
        s1a += x;
        s2a += beta[r] * x;
    }
    atomicAdd(&g_vec[job * 1024 + col], s1a);
    atomicAdd(&g_vec[job * 1024 + 512 + col], s2a);
}

// ---------------- 6. Grams: G = M^T M per half (split-k, atomic) ----------------
__global__ void k_gram() {
    __shared__ float sa[16][64], sb[16][64];
    int bx = blockIdx.x;
    int job = bx >> 7;                 // 0 Ekd, 1 Egan, 2 Zkd, 3 Zgan
    int rem = bx & 127;
    int ksp = rem >> 4;
    int ti = (rem >> 2) & 3, tj = rem & 3;
    const float* M = (job < 2) ? g_En : g_Zn;
    int coff = (job & 1) * 256;
    int i0 = ti * 64 + coff, j0 = tj * 64 + coff;
    int tid = threadIdx.x;
    int tx = tid & 15, ty = tid >> 4;
    float accv[4][4];
#pragma unroll
    for (int i = 0; i < 4; ++i)
#pragma unroll
        for (int j = 0; j < 4; ++j) accv[i][j] = 0.f;

    int lrow = tid >> 4, lcol = (tid & 15) * 4;
    for (int c = 0; c < 64; ++c) {
        int k0 = ksp * 1024 + c * 16 + lrow;
        *(float4*)&sa[lrow][lcol] = *(const float4*)(M + (size_t)k0 * EDIM + i0 + lcol);
        *(float4*)&sb[lrow][lcol] = *(const float4*)(M + (size_t)k0 * EDIM + j0 + lcol);
        __syncthreads();
#pragma unroll
        for (int r = 0; r < 16; ++r) {
            float av[4], bv[4];
            *(float4*)av = *(const float4*)&sa[r][ty * 4];
            *(float4*)bv = *(const float4*)&sb[r][tx * 4];
#pragma unroll
            for (int i = 0; i < 4; ++i)
#pragma unroll
                for (int j = 0; j < 4; ++j)
                    accv[i][j] = fmaf(av[i], bv[j], accv[i][j]);
        }
        __syncthreads();
    }
    float* Gj = g_G + job * 65536;
#pragma unroll
    for (int i = 0; i < 4; ++i)
#pragma unroll
        for (int j = 0; j < 4; ++j)
            atomicAdd(&Gj[(ti * 64 + ty * 4 + i) * 256 + tj * 64 + tx * 4 + j], accv[i][j]);
}

// ---------------- 7. scan + exact rescore (warp per query) ----------------
__global__ void k_scan(float* __restrict__ out) {
    int w = threadIdx.x >> 5, lane = threadIdx.x & 31;
    int n = blockIdx.x * 8 + w;
    float th = __uint_as_float(g_keyu[n]) + 6.5e-2f;
    const __half2* row = (const __half2*)(g_Dh + (size_t)n * KCB);
    int cand[8]; int nc = 0;
#pragma unroll 8
    for (int i = 0; i < 128; ++i) {
        int p = i * 32 + lane;
        float2 fv = __half22float2(row[p]);
        if (fv.x <= th && nc < 8) cand[nc++] = p * 2;
        if (fv.y <= th && nc < 8) cand[nc++] = p * 2 + 1;
    }
    ull bkey = ~0ull;
    float akd = g_akd[n], agn = g_agan[n];
    const float* zr = g_Zn + (size_t)n * EDIM;
    for (int c2 = 0; c2 < nc; ++c2) {
        int k = cand[c2];
        const float* er = g_En + (size_t)k * EDIM;
        float ck = 0.f, cg = 0.f;
        for (int e = 0; e < SEMD; e += 4) {
            float4 zv = *(const float4*)(zr + e);
            float4 ev = *(const float4*)(er + e);
            ck = fmaf(zv.x, ev.x, ck); ck = fmaf(zv.y, ev.y, ck);
            ck = fmaf(zv.z, ev.z, ck); ck = fmaf(zv.w, ev.w, ck);
        }
        for (int e = SEMD; e < EDIM; e += 4) {
            float4 zv = *(const float4*)(zr + e);
            float4 ev = *(const float4*)(er + e);
            cg = fmaf(zv.x, ev.x, cg); cg = fmaf(zv.y, ev.y, cg);
            cg = fmaf(zv.z, ev.z, cg); cg = fmaf(zv.w, ev.w, cg);
        }
        float d = ((akd + g_bkd[k]) - 2.f * ck) + ((agn + g_bgan[k]) - 2.f * cg);
        ull key = ((ull)__float_as_uint(d) << 32) | (unsigned)k;
        if (key < bkey) bkey = key;
    }
#pragma unroll
    for (int o = 16; o > 0; o >>= 1) {
        ull other = __shfl_xor_sync(0xffffffffu, bkey, o);
        if (other < bkey) bkey = other;
    }
    if (lane == 0) {
        int bi = (int)(unsigned)bkey;
        g_idx[n] = bi;
        out[NQ + 2 + n] = (float)bi;
    }
}

// ---------------- 8. S finalize (identity; single CTA) ----------------
// mean_n sum_k d^2 = (K*A2 + 2*A1*B1 + N*B2 - 4*w1.s1 - 4*w0.s2 + 4*<G_E,G_Z>) / N
__global__ void k_sfin(float* __restrict__ out) {
    __shared__ double tot[12];
    __shared__ double totB2[2];
    int tid = threadIdx.x;
    if (tid < 12) tot[tid] = 0.0;
    if (tid < 2) totB2[tid] = 0.0;
    __syncthreads();
    double p[12];
#pragma unroll
    for (int i = 0; i < 12; ++i) p[i] = 0.0;
    for (int i = tid; i < 65536; i += 256) {
        p[0] += (double)g_G[i] * (double)g_G[2 * 65536 + i];           // <G_Ekd, G_Zkd>
        p[1] += (double)g_G[65536 + i] * (double)g_G[3 * 65536 + i];   // <G_Egan, G_Zgan>
    }
    for (int c = tid; c < 512; c += 256) {
        int h = c >> 8;
        p[2 + h] += (double)g_vec[1536 + c] * (double)g_vec[c];        // w1 . s1
        p[4 + h] += (double)g_vec[1024 + c] * (double)g_vec[512 + c];  // w0 . s2
    }
    for (int n = tid; n < NPOS; n += 256) {
        double ak = g_akd[n], ag = g_agan[n];
        p[6] += ak; p[7] += ak * ak;      // A1_kd, A2_kd
        p[8] += ag; p[9] += ag * ag;      // A1_gan, A2_gan
        double bk = g_bkd[n], bg = g_bgan[n];
        p[10] += bk;                      // B1_kd
        p[11] += bg;                      // B1_gan
    }
    double b2k = 0.0, b2g = 0.0;
    for (int n = tid; n < KCB; n += 256) {
        double bk = g_bkd[n], bg = g_bgan[n];
        b2k += bk * bk; b2g += bg * bg;   // B2
    }
    atomicAdd(&totB2[0], b2k);
    atomicAdd(&totB2[1], b2g);
#pragma unroll
    for (int i = 0; i < 12; ++i) atomicAdd(&tot[i], p[i]);
    __syncthreads();
    if (tid == 0) {
        double N = 8192.0;
        double Skd = (N * tot[7] + 2.0 * tot[6] * tot[10] + N * totB2[0]
                      - 4.0 * tot[2] - 4.0 * tot[4] + 4.0 * tot[0]) / N;
        double Sgn = (N * tot[9] + 2.0 * tot[8] * tot[11] + N * totB2[1]
                      - 4.0 * tot[3] - 4.0 * tot[5] + 4.0 * tot[1]) / N;
        out[NQ]     = (float)Skd;     // mean over n (single division by N)
        out[NQ + 1] = (float)Sgn;
    }
}

// ---------------- 9. z_q gather ----------------
__global__ void k_zq(float* __restrict__ out) {
    int row0 = blockIdx.x * 64;
    int b = row0 >> 10, l0 = row0 & 1023;
    int lq = threadIdx.x & 63, dg = threadIdx.x >> 6;
    int n = row0 + lq;
    int kidx = g_idx[n];
    const float* Erow = g_En + (size_t)kidx * EDIM;
    const float* Zrow = g_Zn + (size_t)n * EDIM;
#pragma unroll 4
    for (int dit = 0; dit < 128; ++dit) {
        int d = dg * 128 + dit;
        float ev = Erow[d];
        float zn = Zrow[d];
        out[((size_t)b * D_ + d) * L_ + l0 + lq] = zn + (ev - zn);
    }
}

extern "C" void kernel_launch(void* const* d_in, const int* in_sizes, int n_in,
                              void* d_out, int out_size) {
    (void)in_sizes; (void)n_in; (void)out_size;
    const float* z    = (const float*)d_in[0];
    const float* ekd  = (const float*)d_in[1];
    const float* egan = (const float*)d_in[2];
    float* out = (float*)d_out;

    static int inited = 0;
    if (!inited) {
        cudaFuncSetAttribute(k_gemm_mma, cudaFuncAttributeMaxDynamicSharedMemorySize, 4 * STG4);
        inited = 1;
    }

    k_prep<<<1024 + 256, 256>>>(z, ekd, egan);
    k_zfinal<<<NPOS / 256, 256>>>();
    k_ztrans<<<dim3(16, 32, 8), dim3(32, 8)>>>(z);
    k_gemm_mma<<<4096, 256, 4 * STG4>>>();
    k_colsum<<<64, 256>>>();
    k_gram<<<512, 256>>>();
    k_scan<<<NPOS / 8, 256>>>(out);
    k_sfin<<<1, 256>>>(out);
    k_zq<<<128, 256>>>(out);
}

// round 11
// speedup vs baseline: 1.4242x; 1.4242x over previous
#include <cuda_runtime.h>
#include <cuda_bf16.h>
#include <cuda_fp16.h>
#include <math.h>
#include <stdint.h>

#define B_    8
#define D_    512
#define L_    1024
#define NPOS  8192
#define KCB   8192
#define EDIM  512
#define SEMD  256
#define NQ    4194304

typedef unsigned long long ull;

// ---------------- scratch ----------------
static __device__ float g_Zn [NPOS * EDIM];          // (n, e) fp32 exact
static __device__ float g_ZnT[EDIM * NPOS];          // (e, n) fp32 exact
static __device__ char  g_ZnQ[NPOS * EDIM];          // (n, e) int8
static __device__ float g_En [KCB * EDIM];           // (k, e) fp32 exact
static __device__ char  g_EnQ[KCB * EDIM];           // (k, e) int8
static __device__ __nv_bfloat16 g_ETb[EDIM * KCB];   // (e, k) bf16
static __device__ __nv_bfloat16 g_ZTb[EDIM * NPOS];  // (e, n) bf16
static __device__ float g_psum[8][NPOS];
static __device__ float g_pmax[8][NPOS];
static __device__ float g_invk[NPOS], g_invg[NPOS];
static __device__ float g_akd[NPOS],  g_agan[NPOS];
static __device__ float g_bkd[KCB],   g_bgan[KCB];
static __device__ float g_a[NPOS], g_b[KCB];
static __device__ float g_sZ[NPOS], g_sE[KCB];
static __device__ __half g_Dh[(size_t)NPOS * KCB];
static __device__ unsigned g_keyu[NPOS];
static __device__ int   g_idx[NPOS];
static __device__ float g_G[4 * 65536];              // Grams: Ekd, Egan, Zkd, Zgan
static __device__ float g_vec[2048];                 // s1E[512] s2E[512] w0Z[512] w1Z[512]
static __device__ float g_Sdot[2];

// ---------------- helpers ----------------
__device__ __forceinline__ float wsum(float s) {
#pragma unroll
    for (int o = 16; o > 0; o >>= 1) s += __shfl_xor_sync(0xffffffffu, s, o);
    return s;
}
__device__ __forceinline__ float wmax(float s) {
#pragma unroll
    for (int o = 16; o > 0; o >>= 1) s = fmaxf(s, __shfl_xor_sync(0xffffffffu, s, o));
    return s;
}
__device__ __forceinline__ unsigned s2u(const void* p) {
    unsigned a;
    asm("{ .reg .u64 t; cvta.to.shared.u64 t, %1; cvt.u32.u64 %0, t; }" : "=r"(a) : "l"(p));
    return a;
}
__device__ __forceinline__ void cpasync16(unsigned s, const void* g) {
    asm volatile("cp.async.cg.shared.global [%0], [%1], 16;\n" :: "r"(s), "l"(g));
}
__device__ __forceinline__ void ldsm4(unsigned addr, unsigned &r0, unsigned &r1,
                                      unsigned &r2, unsigned &r3) {
    asm volatile("ldmatrix.sync.aligned.m8n8.x4.shared.b16 {%0,%1,%2,%3}, [%4];"
                 : "=r"(r0), "=r"(r1), "=r"(r2), "=r"(r3) : "r"(addr));
}
__device__ __forceinline__ void mma_s8(int* c, unsigned a0, unsigned a1, unsigned a2,
                                       unsigned a3, unsigned b0, unsigned b1) {
    asm volatile("mma.sync.aligned.m16n8k32.row.col.s32.s8.s8.s32 "
                 "{%0,%1,%2,%3}, {%4,%5,%6,%7}, {%8,%9}, {%0,%1,%2,%3};"
                 : "+r"(c[0]), "+r"(c[1]), "+r"(c[2]), "+r"(c[3])
                 : "r"(a0), "r"(a1), "r"(a2), "r"(a3), "r"(b0), "r"(b1));
}
__device__ __forceinline__ void mma_bf16(float* c, unsigned a0, unsigned a1, unsigned a2,
                                         unsigned a3, unsigned b0, unsigned b1) {
    asm volatile("mma.sync.aligned.m16n8k16.row.col.f32.bf16.bf16.f32 "
                 "{%0,%1,%2,%3}, {%4,%5,%6,%7}, {%8,%9}, {%0,%1,%2,%3};"
                 : "+f"(c[0]), "+f"(c[1]), "+f"(c[2]), "+f"(c[3])
                 : "r"(a0), "r"(a1), "r"(a2), "r"(a3), "r"(b0), "r"(b1));
}

// ---------------- 1. prep: emb normalize+quant+ET-bf16 | z sumsq+max ----------------
__global__ void k_prep(const float* __restrict__ z, const float* __restrict__ ekd,
                       const float* __restrict__ egan) {
    int bid = blockIdx.x;
    if (bid < 1024) {
        __shared__ __nv_bfloat16 smE[EDIM * 8];
        int w = threadIdx.x >> 5, lane = threadIdx.x & 31;
        int k = bid * 8 + w;
        const float* pk = ekd + (size_t)k * SEMD;
        const float* pg = egan + (size_t)k * SEMD;
        float v[8], u[8]; float sk = 0.f, sg = 0.f;
#pragma unroll
        for (int j = 0; j < 8; ++j) {
            v[j] = pk[lane + j * 32]; sk += v[j] * v[j];
            u[j] = pg[lane + j * 32]; sg += u[j] * u[j];
        }
        sk = wsum(sk); sg = wsum(sg);
        float ik = 1.f / fmaxf(sqrtf(sk), 1e-12f);
        float ig = 1.f / fmaxf(sqrtf(sg), 1e-12f);
        float m = 0.f, tk = 0.f, tg = 0.f;
#pragma unroll
        for (int j = 0; j < 8; ++j) {
            v[j] *= ik; u[j] *= ig;
            m = fmaxf(m, fmaxf(fabsf(v[j]), fabsf(u[j])));
            tk += v[j] * v[j]; tg += u[j] * u[j];
        }
        m = wmax(m); tk = wsum(tk); tg = wsum(tg);
        float qs = 127.f / fmaxf(m, 1e-20f);
#pragma unroll
        for (int j = 0; j < 8; ++j) {
            int e1 = lane + j * 32;
            size_t o = (size_t)k * EDIM + e1;
            g_En[o] = v[j];          g_EnQ[o] = (char)__float2int_rn(v[j] * qs);
            g_En[o + SEMD] = u[j];   g_EnQ[o + SEMD] = (char)__float2int_rn(u[j] * qs);
            smE[e1 * 8 + w] = __float2bfloat16_rn(v[j]);
            smE[(e1 + SEMD) * 8 + w] = __float2bfloat16_rn(u[j]);
        }
        if (lane == 0) {
            g_bkd[k] = tk; g_bgan[k] = tg;
            g_b[k] = tk + tg;
            g_sE[k] = m * (1.f / 127.f);
        }
        __syncthreads();
        int t = threadIdx.x, k0 = bid * 8;
#pragma unroll
        for (int rr = 0; rr < 2; ++rr) {
            int e = t * 2 + rr;
            *(uint4*)(g_ETb + (size_t)e * KCB + k0) = *(const uint4*)&smE[e * 8];
        }
    } else {
        int i = bid - 1024;
        int l = (i & 3) * 256 + threadIdx.x;
        int b = (i >> 2) & 7, seg = i >> 5;
        const float* p = z + (size_t)b * D_ * L_ + (size_t)seg * 64 * L_ + l;
        float s = 0.f, m = 0.f;
#pragma unroll 8
        for (int d = 0; d < 64; ++d) {
            float v = p[(size_t)d * L_];
            s += v * v; m = fmaxf(m, fabsf(v));
        }
        g_psum[seg][b * L_ + l] = s;
        g_pmax[seg][b * L_ + l] = m;
    }
}

// ---------------- 2. finalize norms/scales + zero scratch ----------------
__global__ void k_zfinal() {
    int n = blockIdx.x * 256 + threadIdx.x;
    float s = g_psum[0][n] + g_psum[1][n] + g_psum[2][n] + g_psum[3][n];
    float inv = 1.f / fmaxf(sqrtf(s), 1e-12f);
    g_invk[n] = inv;
    float akd = s * inv * inv; g_akd[n] = akd;
    float mk = fmaxf(fmaxf(g_pmax[0][n], g_pmax[1][n]), fmaxf(g_pmax[2][n], g_pmax[3][n])) * inv;
    float s2 = g_psum[4][n] + g_psum[5][n] + g_psum[6][n] + g_psum[7][n];
    float inv2 = 1.f / fmaxf(sqrtf(s2), 1e-12f);
    g_invg[n] = inv2;
    float agan = s2 * inv2 * inv2; g_agan[n] = agan;
    float mg = fmaxf(fmaxf(g_pmax[4][n], g_pmax[5][n]), fmaxf(g_pmax[6][n], g_pmax[7][n])) * inv2;
    g_a[n] = akd + agan;
    g_sZ[n] = fmaxf(mk, mg) * (1.f / 127.f);
    g_keyu[n] = 0xFFFFFFFFu;
    int base = n * 32;
#pragma unroll
    for (int i = 0; i < 32; ++i) g_G[base + i] = 0.f;
    if (n < 2048) g_vec[n] = 0.f;
    if (n < 2) g_Sdot[n] = 0.f;
}

// ---------------- 3. transpose + normalize + quantize z; write Zn/ZnT/ZTb/ZnQ ----------------
__global__ void k_ztrans(const float* __restrict__ z) {
    __shared__ float s[32][33];
    __shared__ float invA[32], rqA[32];
    int d0 = blockIdx.x * 32, l0 = blockIdx.y * 32, b = blockIdx.z;
    int tx = threadIdx.x, ty = threadIdx.y;
    int n0 = b * L_ + l0;
    bool kdh = (d0 < SEMD);
    if (ty == 0) invA[tx] = kdh ? g_invk[n0 + tx] : g_invg[n0 + tx];
    if (ty == 1) rqA[tx] = 1.f / g_sZ[n0 + tx];
#pragma unroll
    for (int q = 0; q < 4; ++q) {
        int dy = ty * 4 + q;
        s[dy][tx] = z[((size_t)b * D_ + d0 + dy) * L_ + l0 + tx];
    }
    __syncthreads();
#pragma unroll
    for (int q = 0; q < 4; ++q) {
        int lr = ty * 4 + q;
        int n = n0 + lr;
        float v = s[tx][lr] * invA[lr];
        size_t o = (size_t)n * EDIM + d0 + tx;
        g_Zn[o] = v;
        g_ZnQ[o] = (char)__float2int_rn(v * rqA[lr]);
    }
#pragma unroll
    for (int q = 0; q < 4; ++q) {
        int dy = ty * 4 + q;
        float v = s[dy][tx] * invA[tx];
        size_t o = (size_t)(d0 + dy) * NPOS + n0 + tx;
        g_ZnT[o] = v;
        g_ZTb[o] = __float2bfloat16_rn(v);
    }
}

// ---------------- 4. int8 mma GEMM 128x128, warp 32x64, 4-stage, 2 CTAs/SM ----------------
#define STG4 20480
__global__ void __launch_bounds__(256, 2) k_gemm_mma() {
    extern __shared__ char dsm[];

    const int tid = threadIdx.x, lane = tid & 31, w = tid >> 5;
    const int bid = blockIdx.x;
    const int sup = bid >> 8, loc = bid & 255;
    const int kt = ((sup & 3) << 4) | (loc & 15);
    const int rt = ((sup >> 2) << 4) | (loc >> 4);
    const int row0 = rt * 128, k0 = kt * 128;
    const int wm = w & 3, wn = w >> 2;

    unsigned sbase = s2u(dsm);

    auto load_chunk = [&](int c) {
        int st = c & 3;
        int e0 = c * 64;
        const char* Ag = g_ZnQ + (size_t)row0 * EDIM + e0;
        const char* Bg = g_EnQ + (size_t)k0 * EDIM + e0;
        unsigned ab = sbase + st * STG4;
        unsigned bb = ab + 10240;
#pragma unroll
        for (int i = 0; i < 2; ++i) {
            int q = tid + i * 256; int r = q >> 2, ch = q & 3;
            cpasync16(ab + r * 80 + ch * 16, Ag + (size_t)r * EDIM + ch * 16);
        }
#pragma unroll
        for (int i = 0; i < 2; ++i) {
            int q = tid + i * 256; int r = q >> 2, ch = q & 3;
            cpasync16(bb + r * 80 + ch * 16, Bg + (size_t)r * EDIM + ch * 16);
        }
        asm volatile("cp.async.commit_group;" ::: "memory");
    };

    int acc[2][8][4];
#pragma unroll
    for (int t = 0; t < 2; ++t)
#pragma unroll
        for (int j = 0; j < 8; ++j)
#pragma unroll
            for (int q = 0; q < 4; ++q) acc[t][j][q] = 0;

    const int lr = lane & 7, lg = lane >> 3;

    auto compute = [&](int st) {
        unsigned ab = sbase + st * STG4;
        unsigned bb = ab + 10240;
#pragma unroll
        for (int s = 0; s < 2; ++s) {
            unsigned a0[2], a1[2], a2[2], a3[2];
#pragma unroll
            for (int t = 0; t < 2; ++t) {
                int row = wm * 32 + t * 16 + lr + 8 * (lg & 1);
                int col = s * 16 + 8 * (lg >> 1);
                ldsm4(ab + row * 80 + col * 2, a0[t], a1[t], a2[t], a3[t]);
            }
            unsigned bf[8][2];
#pragma unroll
            for (int jp = 0; jp < 4; ++jp) {
                int brow = wn * 64 + (jp * 2 + (lg >> 1)) * 8 + lr;
                int bcol = s * 16 + 8 * (lg & 1);
                ldsm4(bb + brow * 80 + bcol * 2,
                      bf[jp * 2][0], bf[jp * 2][1], bf[jp * 2 + 1][0], bf[jp * 2 + 1][1]);
            }
#pragma unroll
            for (int t = 0; t < 2; ++t)
#pragma unroll
                for (int j = 0; j < 8; ++j)
                    mma_s8(acc[t][j], a0[t], a1[t], a2[t], a3[t], bf[j][0], bf[j][1]);
        }
    };

    load_chunk(0); load_chunk(1); load_chunk(2);
#pragma unroll 1
    for (int c = 0; c < 8; ++c) {
        asm volatile("cp.async.wait_group 2;" ::: "memory");
        __syncthreads();
        if (c + 3 < 8) load_chunk(c + 3);
        compute(c & 3);
    }

    const int lq = lane >> 2, lp = lane & 3;
    const int kb = k0 + wn * 64 + lp * 2;
#pragma unroll
    for (int t = 0; t < 2; ++t) {
        int rA = row0 + wm * 32 + t * 16 + lq;
#pragma unroll
        for (int h = 0; h < 2; ++h) {
            int rr = rA + 8 * h;
            float a_ = g_a[rr];
            float tz = 2.f * g_sZ[rr];
            unsigned rmin = 0xFFFFFFFFu;
            __half* drow = g_Dh + (size_t)rr * KCB;
#pragma unroll
            for (int j = 0; j < 8; ++j) {
                int kk = kb + j * 8;
                float d0 = (a_ + g_b[kk])     - tz * g_sE[kk]     * (float)acc[t][j][2 * h];
                float d1 = (a_ + g_b[kk + 1]) - tz * g_sE[kk + 1] * (float)acc[t][j][2 * h + 1];
                rmin = min(rmin, min(__float_as_uint(d0), __float_as_uint(d1)));
                *(__half2*)(drow + kk) = __floats2half2_rn(d0, d1);
            }
            rmin = min(rmin, __shfl_xor_sync(0xffffffffu, rmin, 1));
            rmin = min(rmin, __shfl_xor_sync(0xffffffffu, rmin, 2));
            if (lp == 0) atomicMin(&g_keyu[rr], rmin);
        }
    }
}

// ---------------- 5. Grams via bf16 mma: G = MT * MT^T (contraction over cols) ----------------
__global__ void __launch_bounds__(256, 2) k_gram() {
    extern __shared__ char gsm[];
    const int tid = threadIdx.x, lane = tid & 31, w = tid >> 5;
    const int x = blockIdx.x;
    const int it = (x >> 1) & 1, jt = x & 1;
    const int job = (x >> 2) & 3;
    const int ks = x >> 4;                  // 0..15
    const __nv_bfloat16* Mp = (job < 2) ? g_ETb : g_ZTb;
    const int rowbase = (job & 1) * 256;
    const __nv_bfloat16* Abase_ = Mp + (size_t)(rowbase + it * 128) * KCB;
    const __nv_bfloat16* Bbase_ = Mp + (size_t)(rowbase + jt * 128) * KCB;
    const int n00 = ks * 512;
    const int wm = w & 3, wn = w >> 2;

    unsigned sbase = s2u(gsm);

    auto load_chunk = [&](int c) {
        int st = c & 3;
        int off = n00 + c * 32;
        unsigned ab = sbase + st * STG4;
        unsigned bb = ab + 10240;
#pragma unroll
        for (int i = 0; i < 2; ++i) {
            int q = tid + i * 256; int r = q >> 2, ch = q & 3;
            cpasync16(ab + r * 80 + ch * 16, Abase_ + (size_t)r * KCB + off + ch * 8);
        }
#pragma unroll
        for (int i = 0; i < 2; ++i) {
            int q = tid + i * 256; int r = q >> 2, ch = q & 3;
            cpasync16(bb + r * 80 + ch * 16, Bbase_ + (size_t)r * KCB + off + ch * 8);
        }
        asm volatile("cp.async.commit_group;" ::: "memory");
    };

    float acc[2][8][4];
#pragma unroll
    for (int t = 0; t < 2; ++t)
#pragma unroll
        for (int j = 0; j < 8; ++j)
#pragma unroll
            for (int q = 0; q < 4; ++q) acc[t][j][q] = 0.f;

    const int lr = lane & 7, lg = lane >> 3;

    auto compute = [&](int st) {
        unsigned ab = sbase + st * STG4;
        unsigned bb = ab + 10240;
#pragma unroll
        for (int s = 0; s < 2; ++s) {
            unsigned a0[2], a1[2], a2[2], a3[2];
#pragma unroll
            for (int t = 0; t < 2; ++t) {
                int row = wm * 32 + t * 16 + lr + 8 * (lg & 1);
                int col = s * 16 + 8 * (lg >> 1);
                ldsm4(ab + row * 80 + col * 2, a0[t], a1[t], a2[t], a3[t]);
            }
            unsigned bf[8][2];
#pragma unroll
            for (int jp = 0; jp < 4; ++jp) {
                int brow = wn * 64 + (jp * 2 + (lg >> 1)) * 8 + lr;
                int bcol = s * 16 + 8 * (lg & 1);
                ldsm4(bb + brow * 80 + bcol * 2,
                      bf[jp * 2][0], bf[jp * 2][1], bf[jp * 2 + 1][0], bf[jp * 2 + 1][1]);
            }
#pragma unroll
            for (int t = 0; t < 2; ++t)
#pragma unroll
                for (int j = 0; j < 8; ++j)
                    mma_bf16(acc[t][j], a0[t], a1[t], a2[t], a3[t], bf[j][0], bf[j][1]);
        }
    };

    load_chunk(0); load_chunk(1); load_chunk(2);
#pragma unroll 1
    for (int c = 0; c < 16; ++c) {
        asm volatile("cp.async.wait_group 2;" ::: "memory");
        __syncthreads();
        if (c + 3 < 16) load_chunk(c + 3);
        compute(c & 3);
    }

    float* Gj = g_G + job * 65536;
    const int lq = lane >> 2, lp = lane & 3;
    const int jb = jt * 128 + wn * 64 + lp * 2;
#pragma unroll
    for (int t = 0; t < 2; ++t) {
        int rA = it * 128 + wm * 32 + t * 16 + lq;
#pragma unroll
        for (int h = 0; h < 2; ++h) {
            int rr = rA + 8 * h;
#pragma unroll
            for (int j = 0; j < 8; ++j) {
                int kk = jb + j * 8;
                atomicAdd(&Gj[rr * 256 + kk],     acc[t][j][2 * h]);
                atomicAdd(&Gj[rr * 256 + kk + 1], acc[t][j][2 * h + 1]);
            }
        }
    }
}

// ---------------- 6. column sums (coalesced): s1/s2 for E, w0/w1 for Z ----------------
__global__ void k_colsum() {
    int job = blockIdx.x >> 7;               // 0=E, 1=Z
    int r0 = (blockIdx.x & 127) * 64;
    const float* M = job ? g_Zn : g_En;
    const float* betak = job ? g_akd : g_bkd;
    const float* betag = job ? g_agan : g_bgan;
    int t = threadIdx.x;
    float s1a = 0.f, s2a = 0.f, s1b = 0.f, s2b = 0.f;
    for (int r = r0; r < r0 + 64; ++r) {
        float bk = betak[r], bg = betag[r];
        float x1 = M[(size_t)r * EDIM + t];
        float x2 = M[(size_t)r * EDIM + t + 256];
        s1a += x1; s2a += bk * x1;
        s1b += x2; s2b += bg * x2;
    }
    atomicAdd(&g_vec[job * 1024 + t],       s1a);
    atomicAdd(&g_vec[job * 1024 + 512 + t], s2a);
    atomicAdd(&g_vec[job * 1024 + 256 + t],       s1b);
    atomicAdd(&g_vec[job * 1024 + 512 + 256 + t], s2b);
}

// ---------------- 7. scan + exact rescore (warp per query) ----------------
__global__ void k_scan(float* __restrict__ out) {
    int w = threadIdx.x >> 5, lane = threadIdx.x & 31;
    int n = blockIdx.x * 8 + w;
    float th = __uint_as_float(g_keyu[n]) + 6.5e-2f;
    const __half2* row = (const __half2*)(g_Dh + (size_t)n * KCB);
    int cand[8]; int nc = 0;
#pragma unroll 8
    for (int i = 0; i < 128; ++i) {
        int p = i * 32 + lane;
        float2 fv = __half22float2(row[p]);
        if (fv.x <= th && nc < 8) cand[nc++] = p * 2;
        if (fv.y <= th && nc < 8) cand[nc++] = p * 2 + 1;
    }
    ull bkey = ~0ull;
    float akd = g_akd[n], agn = g_agan[n];
    const float* zr = g_Zn + (size_t)n * EDIM;
    for (int c2 = 0; c2 < nc; ++c2) {
        int k = cand[c2];
        const float* er = g_En + (size_t)k * EDIM;
        float ck = 0.f, cg = 0.f;
        for (int e = 0; e < SEMD; e += 4) {
            float4 zv = *(const float4*)(zr + e);
            float4 ev = *(const float4*)(er + e);
            ck = fmaf(zv.x, ev.x, ck); ck = fmaf(zv.y, ev.y, ck);
            ck = fmaf(zv.z, ev.z, ck); ck = fmaf(zv.w, ev.w, ck);
        }
        for (int e = SEMD; e < EDIM; e += 4) {
            float4 zv = *(const float4*)(zr + e);
            float4 ev = *(const float4*)(er + e);
            cg = fmaf(zv.x, ev.x, cg); cg = fmaf(zv.y, ev.y, cg);
            cg = fmaf(zv.z, ev.z, cg); cg = fmaf(zv.w, ev.w, cg);
        }
        float d = ((akd + g_bkd[k]) - 2.f * ck) + ((agn + g_bgan[k]) - 2.f * cg);
        ull key = ((ull)__float_as_uint(d) << 32) | (unsigned)k;
        if (key < bkey) bkey = key;
    }
#pragma unroll
    for (int o = 16; o > 0; o >>= 1) {
        ull other = __shfl_xor_sync(0xffffffffu, bkey, o);
        if (other < bkey) bkey = other;
    }
    if (lane == 0) {
        int bi = (int)(unsigned)bkey;
        g_idx[n] = bi;
        out[NQ + 2 + n] = (float)bi;
    }
}

// ---------------- 8. <G_E, G_Z> partial dots ----------------
__global__ void k_sdot() {
    int t = blockIdx.x * 256 + threadIdx.x;   // 16384 threads
    float p0 = 0.f, p1 = 0.f;
    for (int i = t; i < 65536; i += 16384) {
        p0 += g_G[i] * g_G[131072 + i];
        p1 += g_G[65536 + i] * g_G[196608 + i];
    }
    p0 = wsum(p0); p1 = wsum(p1);
    if ((threadIdx.x & 31) == 0) {
        atomicAdd(&g_Sdot[0], p0);
        atomicAdd(&g_Sdot[1], p1);
    }
}

// ---------------- 9. S finalize ----------------
__global__ void k_sfin(float* __restrict__ out) {
    __shared__ float red[12][8];
    int tid = threadIdx.x, lane = tid & 31, w = tid >> 5;
    float p[12];
#pragma unroll
    for (int i = 0; i < 12; ++i) p[i] = 0.f;
    for (int n = tid; n < NPOS; n += 256) {
        float ak = g_akd[n], ag = g_agan[n];
        float bk = g_bkd[n], bg = g_bgan[n];
        p[0] += ak; p[1] += ak * ak;
        p[2] += ag; p[3] += ag * ag;
        p[4] += bk; p[5] += bk * bk;
        p[6] += bg; p[7] += bg * bg;
    }
    // dots over 512 cols; each thread covers 2 cols
    {
        int c = tid;                      // 0..255 (kd cols)
        p[8]  += g_vec[1536 + c] * g_vec[c];             // w1.s1 kd
        p[10] += g_vec[1024 + c] * g_vec[512 + c];       // w0.s2 kd
        int c2 = tid + 256;               // gan cols
        p[9]  += g_vec[1536 + c2] * g_vec[c2];           // w1.s1 gan
        p[11] += g_vec[1024 + c2] * g_vec[512 + c2];     // w0.s2 gan
    }
#pragma unroll
    for (int i = 0; i < 12; ++i) {
        float v = wsum(p[i]);
        if (lane == 0) red[i][w] = v;
    }
    __syncthreads();
    if (tid == 0) {
        double tt[12];
#pragma unroll
        for (int i = 0; i < 12; ++i) {
            double s = 0.0;
            for (int j = 0; j < 8; ++j) s += (double)red[i][j];
            tt[i] = s;
        }
        double N = 8192.0;
        double Skd = (N * tt[1] + 2.0 * tt[0] * tt[4] + N * tt[5]
                      - 4.0 * tt[8] - 4.0 * tt[10] + 4.0 * (double)g_Sdot[0]) / N;
        double Sgn = (N * tt[3] + 2.0 * tt[2] * tt[6] + N * tt[7]
                      - 4.0 * tt[9] - 4.0 * tt[11] + 4.0 * (double)g_Sdot[1]) / N;
        out[NQ]     = (float)Skd;
        out[NQ + 1] = (float)Sgn;
    }
}

// ---------------- 10. z_q gather (tiled transpose, coalesced) ----------------
__global__ void k_zq(float* __restrict__ out) {
    __shared__ float sm[64][133];
    __shared__ int sidx[64];
    int n0 = blockIdx.x * 64;
    int b = n0 >> 10, l0 = n0 & 1023;
    int t = threadIdx.x;
    if (t < 64) sidx[t] = g_idx[n0 + t];
    __syncthreads();
    int w = t >> 5, lane = t & 31;
    int dl0 = t >> 6, nn2 = t & 63;
#pragma unroll 1
    for (int dc = 0; dc < 4; ++dc) {
        int d0 = dc * 128;
#pragma unroll
        for (int i = 0; i < 8; ++i) {
            int nn = w * 8 + i;
            float4 v = ((const float4*)(g_En + (size_t)sidx[nn] * EDIM + d0))[lane];
            sm[nn][lane * 4 + 0] = v.x;
            sm[nn][lane * 4 + 1] = v.y;
            sm[nn][lane * 4 + 2] = v.z;
            sm[nn][lane * 4 + 3] = v.w;
        }
        __syncthreads();
#pragma unroll 8
        for (int pp = 0; pp < 128; pp += 4) {
            int d = d0 + pp + dl0;
            float zn = g_ZnT[(size_t)d * NPOS + n0 + nn2];
            float ev = sm[nn2][pp + dl0];
            out[((size_t)(b * D_ + d)) * L_ + l0 + nn2] = zn + (ev - zn);
        }
        __syncthreads();
    }
}

extern "C" void kernel_launch(void* const* d_in, const int* in_sizes, int n_in,
                              void* d_out, int out_size) {
    (void)in_sizes; (void)n_in; (void)out_size;
    const float* z    = (const float*)d_in[0];
    const float* ekd  = (const float*)d_in[1];
    const float* egan = (const float*)d_in[2];
    float* out = (float*)d_out;

    static int inited = 0;
    if (!inited) {
        cudaFuncSetAttribute(k_gemm_mma, cudaFuncAttributeMaxDynamicSharedMemorySize, 4 * STG4);
        cudaFuncSetAttribute(k_gram,     cudaFuncAttributeMaxDynamicSharedMemorySize, 4 * STG4);
        inited = 1;
    }

    k_prep<<<1024 + 256, 256>>>(z, ekd, egan);
    k_zfinal<<<NPOS / 256, 256>>>();
    k_ztrans<<<dim3(16, 32, 8), dim3(32, 8)>>>(z);
    k_gemm_mma<<<4096, 256, 4 * STG4>>>();
    k_gram<<<256, 256, 4 * STG4>>>();
    k_colsum<<<256, 256>>>();
    k_scan<<<NPOS / 8, 256>>>(out);
    k_sdot<<<64, 256>>>();
    k_sfin<<<1, 256>>>(out);
    k_zq<<<128, 256>>>(out);
}

// round 12
// speedup vs baseline: 1.6177x; 1.1359x over previous
#include <cuda_runtime.h>
#include <cuda_bf16.h>
#include <cuda_fp16.h>
#include <math.h>
#include <stdint.h>

#define B_    8
#define D_    512
#define L_    1024
#define NPOS  8192
#define KCB   8192
#define EDIM  512
#define SEMD  256
#define NQ    4194304

typedef unsigned long long ull;

// ---------------- scratch ----------------
static __device__ float g_Zn [NPOS * EDIM];          // (n, e) fp32 exact
static __device__ float g_ZnT[EDIM * NPOS];          // (e, n) fp32 exact
static __device__ char  g_ZnQ[NPOS * EDIM];          // (n, e) int8
static __device__ float g_En [KCB * EDIM];           // (k, e) fp32 exact
static __device__ char  g_EnQ[KCB * EDIM];           // (k, e) int8
static __device__ __nv_bfloat16 g_ETb[EDIM * KCB];   // (e, k) bf16
static __device__ __nv_bfloat16 g_ZTb[EDIM * NPOS];  // (e, n) bf16
static __device__ float g_psum[8][NPOS];
static __device__ float g_pmax[8][NPOS];
static __device__ float g_invk[NPOS], g_invg[NPOS];
static __device__ float g_akd[NPOS],  g_agan[NPOS];
static __device__ float g_bkd[KCB],   g_bgan[KCB];
static __device__ float g_a[NPOS], g_b[KCB];
static __device__ float g_sZ[NPOS], g_sE[KCB];
static __device__ __half g_Dh[(size_t)NPOS * KCB];
static __device__ unsigned g_keyu[NPOS];
static __device__ int   g_idx[NPOS];
static __device__ float g_Gp[128 * 16384];           // Gram partials: (job,tile,ks) tiles
static __device__ float g_vec[2048];                 // s1E s2E | w0Z w1Z
static __device__ float g_Sdot[2];

// ---------------- helpers ----------------
__device__ __forceinline__ float wsum(float s) {
#pragma unroll
    for (int o = 16; o > 0; o >>= 1) s += __shfl_xor_sync(0xffffffffu, s, o);
    return s;
}
__device__ __forceinline__ float wmax(float s) {
#pragma unroll
    for (int o = 16; o > 0; o >>= 1) s = fmaxf(s, __shfl_xor_sync(0xffffffffu, s, o));
    return s;
}
__device__ __forceinline__ unsigned s2u(const void* p) {
    unsigned a;
    asm("{ .reg .u64 t; cvta.to.shared.u64 t, %1; cvt.u32.u64 %0, t; }" : "=r"(a) : "l"(p));
    return a;
}
__device__ __forceinline__ void cpasync16(unsigned s, const void* g) {
    asm volatile("cp.async.cg.shared.global [%0], [%1], 16;\n" :: "r"(s), "l"(g));
}
__device__ __forceinline__ void ldsm4(unsigned addr, unsigned &r0, unsigned &r1,
                                      unsigned &r2, unsigned &r3) {
    asm volatile("ldmatrix.sync.aligned.m8n8.x4.shared.b16 {%0,%1,%2,%3}, [%4];"
                 : "=r"(r0), "=r"(r1), "=r"(r2), "=r"(r3) : "r"(addr));
}
__device__ __forceinline__ void mma_s8(int* c, unsigned a0, unsigned a1, unsigned a2,
                                       unsigned a3, unsigned b0, unsigned b1) {
    asm volatile("mma.sync.aligned.m16n8k32.row.col.s32.s8.s8.s32 "
                 "{%0,%1,%2,%3}, {%4,%5,%6,%7}, {%8,%9}, {%0,%1,%2,%3};"
                 : "+r"(c[0]), "+r"(c[1]), "+r"(c[2]), "+r"(c[3])
                 : "r"(a0), "r"(a1), "r"(a2), "r"(a3), "r"(b0), "r"(b1));
}
__device__ __forceinline__ void mma_bf16(float* c, unsigned a0, unsigned a1, unsigned a2,
                                         unsigned a3, unsigned b0, unsigned b1) {
    asm volatile("mma.sync.aligned.m16n8k16.row.col.f32.bf16.bf16.f32 "
                 "{%0,%1,%2,%3}, {%4,%5,%6,%7}, {%8,%9}, {%0,%1,%2,%3};"
                 : "+f"(c[0]), "+f"(c[1]), "+f"(c[2]), "+f"(c[3])
                 : "r"(a0), "r"(a1), "r"(a2), "r"(a3), "r"(b0), "r"(b1));
}

// ---------------- 1. prep: emb normalize+quant+ET-bf16 | z sumsq+max ----------------
__global__ void k_prep(const float* __restrict__ z, const float* __restrict__ ekd,
                       const float* __restrict__ egan) {
    int bid = blockIdx.x;
    if (bid < 1024) {
        __shared__ __nv_bfloat16 smE[EDIM * 8];
        int w = threadIdx.x >> 5, lane = threadIdx.x & 31;
        int k = bid * 8 + w;
        const float* pk = ekd + (size_t)k * SEMD;
        const float* pg = egan + (size_t)k * SEMD;
        float v[8], u[8]; float sk = 0.f, sg = 0.f;
#pragma unroll
        for (int j = 0; j < 8; ++j) {
            v[j] = pk[lane + j * 32]; sk += v[j] * v[j];
            u[j] = pg[lane + j * 32]; sg += u[j] * u[j];
        }
        sk = wsum(sk); sg = wsum(sg);
        float ik = 1.f / fmaxf(sqrtf(sk), 1e-12f);
        float ig = 1.f / fmaxf(sqrtf(sg), 1e-12f);
        float m = 0.f, tk = 0.f, tg = 0.f;
#pragma unroll
        for (int j = 0; j < 8; ++j) {
            v[j] *= ik; u[j] *= ig;
            m = fmaxf(m, fmaxf(fabsf(v[j]), fabsf(u[j])));
            tk += v[j] * v[j]; tg += u[j] * u[j];
        }
        m = wmax(m); tk = wsum(tk); tg = wsum(tg);
        float qs = 127.f / fmaxf(m, 1e-20f);
#pragma unroll
        for (int j = 0; j < 8; ++j) {
            int e1 = lane + j * 32;
            size_t o = (size_t)k * EDIM + e1;
            g_En[o] = v[j];          g_EnQ[o] = (char)__float2int_rn(v[j] * qs);
            g_En[o + SEMD] = u[j];   g_EnQ[o + SEMD] = (char)__float2int_rn(u[j] * qs);
            smE[e1 * 8 + w] = __float2bfloat16_rn(v[j]);
            smE[(e1 + SEMD) * 8 + w] = __float2bfloat16_rn(u[j]);
        }
        if (lane == 0) {
            g_bkd[k] = tk; g_bgan[k] = tg;
            g_b[k] = tk + tg;
            g_sE[k] = m * (1.f / 127.f);
        }
        __syncthreads();
        int t = threadIdx.x, k0 = bid * 8;
#pragma unroll
        for (int rr = 0; rr < 2; ++rr) {
            int e = t * 2 + rr;
            *(uint4*)(g_ETb + (size_t)e * KCB + k0) = *(const uint4*)&smE[e * 8];
        }
    } else {
        int i = bid - 1024;
        int l = (i & 3) * 256 + threadIdx.x;
        int b = (i >> 2) & 7, seg = i >> 5;
        const float* p = z + (size_t)b * D_ * L_ + (size_t)seg * 64 * L_ + l;
        float s = 0.f, m = 0.f;
#pragma unroll 8
        for (int d = 0; d < 64; ++d) {
            float v = p[(size_t)d * L_];
            s += v * v; m = fmaxf(m, fabsf(v));
        }
        g_psum[seg][b * L_ + l] = s;
        g_pmax[seg][b * L_ + l] = m;
    }
}

// ---------------- 2. finalize norms/scales + zero scratch ----------------
__global__ void k_zfinal() {
    int n = blockIdx.x * 256 + threadIdx.x;
    float s = g_psum[0][n] + g_psum[1][n] + g_psum[2][n] + g_psum[3][n];
    float inv = 1.f / fmaxf(sqrtf(s), 1e-12f);
    g_invk[n] = inv;
    float akd = s * inv * inv; g_akd[n] = akd;
    float mk = fmaxf(fmaxf(g_pmax[0][n], g_pmax[1][n]), fmaxf(g_pmax[2][n], g_pmax[3][n])) * inv;
    float s2 = g_psum[4][n] + g_psum[5][n] + g_psum[6][n] + g_psum[7][n];
    float inv2 = 1.f / fmaxf(sqrtf(s2), 1e-12f);
    g_invg[n] = inv2;
    float agan = s2 * inv2 * inv2; g_agan[n] = agan;
    float mg = fmaxf(fmaxf(g_pmax[4][n], g_pmax[5][n]), fmaxf(g_pmax[6][n], g_pmax[7][n])) * inv2;
    g_a[n] = akd + agan;
    g_sZ[n] = fmaxf(mk, mg) * (1.f / 127.f);
    g_keyu[n] = 0xFFFFFFFFu;
    if (n < 2048) g_vec[n] = 0.f;
    if (n < 2) g_Sdot[n] = 0.f;
}

// ---------------- 3. transpose + normalize + quantize z ----------------
__global__ void k_ztrans(const float* __restrict__ z) {
    __shared__ float s[32][33];
    __shared__ float invA[32], rqA[32];
    int d0 = blockIdx.x * 32, l0 = blockIdx.y * 32, b = blockIdx.z;
    int tx = threadIdx.x, ty = threadIdx.y;
    int n0 = b * L_ + l0;
    bool kdh = (d0 < SEMD);
    if (ty == 0) invA[tx] = kdh ? g_invk[n0 + tx] : g_invg[n0 + tx];
    if (ty == 1) rqA[tx] = 1.f / g_sZ[n0 + tx];
#pragma unroll
    for (int q = 0; q < 4; ++q) {
        int dy = ty * 4 + q;
        s[dy][tx] = z[((size_t)b * D_ + d0 + dy) * L_ + l0 + tx];
    }
    __syncthreads();
#pragma unroll
    for (int q = 0; q < 4; ++q) {
        int lr = ty * 4 + q;
        int n = n0 + lr;
        float v = s[tx][lr] * invA[lr];
        size_t o = (size_t)n * EDIM + d0 + tx;
        g_Zn[o] = v;
        g_ZnQ[o] = (char)__float2int_rn(v * rqA[lr]);
    }
#pragma unroll
    for (int q = 0; q < 4; ++q) {
        int dy = ty * 4 + q;
        float v = s[dy][tx] * invA[tx];
        size_t o = (size_t)(d0 + dy) * NPOS + n0 + tx;
        g_ZnT[o] = v;
        g_ZTb[o] = __float2bfloat16_rn(v);
    }
}

// ---------------- 4. int8 mma GEMM 128x128, warp 32x64, 4-stage, 2 CTAs/SM ----------------
#define STG4 20480
__global__ void __launch_bounds__(256, 2) k_gemm_mma() {
    extern __shared__ char dsm[];

    const int tid = threadIdx.x, lane = tid & 31, w = tid >> 5;
    const int bid = blockIdx.x;
    const int sup = bid >> 8, loc = bid & 255;
    const int kt = ((sup & 3) << 4) | (loc & 15);
    const int rt = ((sup >> 2) << 4) | (loc >> 4);
    const int row0 = rt * 128, k0 = kt * 128;
    const int wm = w & 3, wn = w >> 2;

    unsigned sbase = s2u(dsm);

    auto load_chunk = [&](int c) {
        int st = c & 3;
        int e0 = c * 64;
        const char* Ag = g_ZnQ + (size_t)row0 * EDIM + e0;
        const char* Bg = g_EnQ + (size_t)k0 * EDIM + e0;
        unsigned ab = sbase + st * STG4;
        unsigned bb = ab + 10240;
#pragma unroll
        for (int i = 0; i < 2; ++i) {
            int q = tid + i * 256; int r = q >> 2, ch = q & 3;
            cpasync16(ab + r * 80 + ch * 16, Ag + (size_t)r * EDIM + ch * 16);
        }
#pragma unroll
        for (int i = 0; i < 2; ++i) {
            int q = tid + i * 256; int r = q >> 2, ch = q & 3;
            cpasync16(bb + r * 80 + ch * 16, Bg + (size_t)r * EDIM + ch * 16);
        }
        asm volatile("cp.async.commit_group;" ::: "memory");
    };

    int acc[2][8][4];
#pragma unroll
    for (int t = 0; t < 2; ++t)
#pragma unroll
        for (int j = 0; j < 8; ++j)
#pragma unroll
            for (int q = 0; q < 4; ++q) acc[t][j][q] = 0;

    const int lr = lane & 7, lg = lane >> 3;

    auto compute = [&](int st) {
        unsigned ab = sbase + st * STG4;
        unsigned bb = ab + 10240;
#pragma unroll
        for (int s = 0; s < 2; ++s) {
            unsigned a0[2], a1[2], a2[2], a3[2];
#pragma unroll
            for (int t = 0; t < 2; ++t) {
                int row = wm * 32 + t * 16 + lr + 8 * (lg & 1);
                int col = s * 16 + 8 * (lg >> 1);
                ldsm4(ab + row * 80 + col * 2, a0[t], a1[t], a2[t], a3[t]);
            }
            unsigned bf[8][2];
#pragma unroll
            for (int jp = 0; jp < 4; ++jp) {
                int brow = wn * 64 + (jp * 2 + (lg >> 1)) * 8 + lr;
                int bcol = s * 16 + 8 * (lg & 1);
                ldsm4(bb + brow * 80 + bcol * 2,
                      bf[jp * 2][0], bf[jp * 2][1], bf[jp * 2 + 1][0], bf[jp * 2 + 1][1]);
            }
#pragma unroll
            for (int t = 0; t < 2; ++t)
#pragma unroll
                for (int j = 0; j < 8; ++j)
                    mma_s8(acc[t][j], a0[t], a1[t], a2[t], a3[t], bf[j][0], bf[j][1]);
        }
    };

    load_chunk(0); load_chunk(1); load_chunk(2);
#pragma unroll 1
    for (int c = 0; c < 8; ++c) {
        asm volatile("cp.async.wait_group 2;" ::: "memory");
        __syncthreads();
        if (c + 3 < 8) load_chunk(c + 3);
        compute(c & 3);
    }

    const int lq = lane >> 2, lp = lane & 3;
    const int kb = k0 + wn * 64 + lp * 2;
#pragma unroll
    for (int t = 0; t < 2; ++t) {
        int rA = row0 + wm * 32 + t * 16 + lq;
#pragma unroll
        for (int h = 0; h < 2; ++h) {
            int rr = rA + 8 * h;
            float a_ = g_a[rr];
            float tz = 2.f * g_sZ[rr];
            unsigned rmin = 0xFFFFFFFFu;
            __half* drow = g_Dh + (size_t)rr * KCB;
#pragma unroll
            for (int j = 0; j < 8; ++j) {
                int kk = kb + j * 8;
                float d0 = (a_ + g_b[kk])     - tz * g_sE[kk]     * (float)acc[t][j][2 * h];
                float d1 = (a_ + g_b[kk + 1]) - tz * g_sE[kk + 1] * (float)acc[t][j][2 * h + 1];
                rmin = min(rmin, min(__float_as_uint(d0), __float_as_uint(d1)));
                *(__half2*)(drow + kk) = __floats2half2_rn(d0, d1);
            }
            rmin = min(rmin, __shfl_xor_sync(0xffffffffu, rmin, 1));
            rmin = min(rmin, __shfl_xor_sync(0xffffffffu, rmin, 2));
            if (lp == 0) atomicMin(&g_keyu[rr], rmin);
        }
    }
}

// ---------------- 5. Grams via bf16 mma, k-split 8, plain stores ----------------
__global__ void __launch_bounds__(256, 2) k_gram() {
    extern __shared__ char gsm[];
    const int tid = threadIdx.x, lane = tid & 31, w = tid >> 5;
    const int x = blockIdx.x;                // 128 CTAs
    const int jt = x & 1, it = (x >> 1) & 1;
    const int job = (x >> 2) & 3;
    const int ks = x >> 4;                   // 0..7
    const __nv_bfloat16* Mp = (job < 2) ? g_ETb : g_ZTb;
    const int rowbase = (job & 1) * 256;
    const __nv_bfloat16* Abase_ = Mp + (size_t)(rowbase + it * 128) * KCB;
    const __nv_bfloat16* Bbase_ = Mp + (size_t)(rowbase + jt * 128) * KCB;
    const int n00 = ks * 1024;
    const int wm = w & 3, wn = w >> 2;

    unsigned sbase = s2u(gsm);

    auto load_chunk = [&](int c) {
        int st = c & 3;
        int off = n00 + c * 32;
        unsigned ab = sbase + st * STG4;
        unsigned bb = ab + 10240;
#pragma unroll
        for (int i = 0; i < 2; ++i) {
            int q = tid + i * 256; int r = q >> 2, ch = q & 3;
            cpasync16(ab + r * 80 + ch * 16, Abase_ + (size_t)r * KCB + off + ch * 8);
        }
#pragma unroll
        for (int i = 0; i < 2; ++i) {
            int q = tid + i * 256; int r = q >> 2, ch = q & 3;
            cpasync16(bb + r * 80 + ch * 16, Bbase_ + (size_t)r * KCB + off + ch * 8);
        }
        asm volatile("cp.async.commit_group;" ::: "memory");
    };

    float acc[2][8][4];
#pragma unroll
    for (int t = 0; t < 2; ++t)
#pragma unroll
        for (int j = 0; j < 8; ++j)
#pragma unroll
            for (int q = 0; q < 4; ++q) acc[t][j][q] = 0.f;

    const int lr = lane & 7, lg = lane >> 3;

    auto compute = [&](int st) {
        unsigned ab = sbase + st * STG4;
        unsigned bb = ab + 10240;
#pragma unroll
        for (int s = 0; s < 2; ++s) {
            unsigned a0[2], a1[2], a2[2], a3[2];
#pragma unroll
            for (int t = 0; t < 2; ++t) {
                int row = wm * 32 + t * 16 + lr + 8 * (lg & 1);
                int col = s * 16 + 8 * (lg >> 1);
                ldsm4(ab + row * 80 + col * 2, a0[t], a1[t], a2[t], a3[t]);
            }
            unsigned bf[8][2];
#pragma unroll
            for (int jp = 0; jp < 4; ++jp) {
                int brow = wn * 64 + (jp * 2 + (lg >> 1)) * 8 + lr;
                int bcol = s * 16 + 8 * (lg & 1);
                ldsm4(bb + brow * 80 + bcol * 2,
                      bf[jp * 2][0], bf[jp * 2][1], bf[jp * 2 + 1][0], bf[jp * 2 + 1][1]);
            }
#pragma unroll
            for (int t = 0; t < 2; ++t)
#pragma unroll
                for (int j = 0; j < 8; ++j)
                    mma_bf16(acc[t][j], a0[t], a1[t], a2[t], a3[t], bf[j][0], bf[j][1]);
        }
    };

    load_chunk(0); load_chunk(1); load_chunk(2);
#pragma unroll 1
    for (int c = 0; c < 32; ++c) {
        asm volatile("cp.async.wait_group 2;" ::: "memory");
        __syncthreads();
        if (c + 3 < 32) load_chunk(c + 3);
        compute(c & 3);
    }

    float* Gp = g_Gp + (size_t)(((job * 4 + it * 2 + jt) * 8) + ks) * 16384;
    const int lq = lane >> 2, lp = lane & 3;
    const int jb = wn * 64 + lp * 2;
#pragma unroll
    for (int t = 0; t < 2; ++t) {
        int rA = wm * 32 + t * 16 + lq;
#pragma unroll
        for (int h = 0; h < 2; ++h) {
            int rr = rA + 8 * h;
#pragma unroll
            for (int j = 0; j < 8; ++j) {
                int kk = jb + j * 8;
                *(float2*)&Gp[rr * 128 + kk] =
                    make_float2(acc[t][j][2 * h], acc[t][j][2 * h + 1]);
            }
        }
    }
}

// ---------------- 6. column sums (coalesced) ----------------
__global__ void k_colsum() {
    int job = blockIdx.x >> 7;               // 0=E, 1=Z
    int r0 = (blockIdx.x & 127) * 64;
    const float* M = job ? g_Zn : g_En;
    const float* betak = job ? g_akd : g_bkd;
    const float* betag = job ? g_agan : g_bgan;
    int t = threadIdx.x;
    float s1a = 0.f, s2a = 0.f, s1b = 0.f, s2b = 0.f;
    for (int r = r0; r < r0 + 64; ++r) {
        float bk = betak[r], bg = betag[r];
        float x1 = M[(size_t)r * EDIM + t];
        float x2 = M[(size_t)r * EDIM + t + 256];
        s1a += x1; s2a += bk * x1;
        s1b += x2; s2b += bg * x2;
    }
    atomicAdd(&g_vec[job * 1024 + t],       s1a);
    atomicAdd(&g_vec[job * 1024 + 512 + t], s2a);
    atomicAdd(&g_vec[job * 1024 + 256 + t],       s1b);
    atomicAdd(&g_vec[job * 1024 + 512 + 256 + t], s2b);
}

// ---------------- 7. scan + warp-cooperative exact rescore ----------------
__global__ void k_scan(float* __restrict__ out) {
    __shared__ int scnt[8];
    __shared__ int slist[8][96];
    int w = threadIdx.x >> 5, lane = threadIdx.x & 31;
    int n = blockIdx.x * 8 + w;
    if (lane == 0) scnt[w] = 0;
    __syncwarp();
    float th = __uint_as_float(g_keyu[n]) + 6.5e-2f;
    const __half2* row = (const __half2*)(g_Dh + (size_t)n * KCB);
#pragma unroll 8
    for (int i = 0; i < 128; ++i) {
        int p = i * 32 + lane;
        float2 fv = __half22float2(row[p]);
        if (fv.x <= th) { int s = atomicAdd(&scnt[w], 1); if (s < 96) slist[w][s] = p * 2; }
        if (fv.y <= th) { int s = atomicAdd(&scnt[w], 1); if (s < 96) slist[w][s] = p * 2 + 1; }
    }
    __syncwarp();
    int nc = min(scnt[w], 96);
    // preload this query's normalized vector fragment (lane covers 16 floats)
    const float* zr = g_Zn + (size_t)n * EDIM;
    float4 zv[4];
#pragma unroll
    for (int q = 0; q < 4; ++q) zv[q] = *(const float4*)(zr + lane * 4 + q * 128);
    float akd = g_akd[n], agn = g_agan[n];
    ull bkey = ~0ull;
    for (int c2 = 0; c2 < nc; ++c2) {
        int k = slist[w][c2];
        const float* er = g_En + (size_t)k * EDIM;
        float ck = 0.f, cg = 0.f;
#pragma unroll
        for (int q = 0; q < 4; ++q) {
            float4 ev = *(const float4*)(er + lane * 4 + q * 128);
            float dd = zv[q].x * ev.x + zv[q].y * ev.y + zv[q].z * ev.z + zv[q].w * ev.w;
            if (q < 2) ck += dd; else cg += dd;
        }
        ck = wsum(ck); cg = wsum(cg);
        float d = ((akd + g_bkd[k]) - 2.f * ck) + ((agn + g_bgan[k]) - 2.f * cg);
        ull key = ((ull)__float_as_uint(d) << 32) | (unsigned)k;
        if (key < bkey) bkey = key;
    }
    if (lane == 0) {
        int bi = (int)(unsigned)bkey;
        g_idx[n] = bi;
        out[NQ + 2 + n] = (float)bi;
    }
}

// ---------------- 8. <G_E, G_Z> from partials ----------------
__global__ void k_sdot() {
    int idx = blockIdx.x * 256 + threadIdx.x;   // 16384 threads
    float p0 = 0.f, p1 = 0.f;
    for (int i = idx; i < 65536; i += 16384) {
        int t4 = i >> 14, locv = i & 16383;
        float e0 = 0.f, z0 = 0.f, e1 = 0.f, z1 = 0.f;
#pragma unroll
        for (int ks = 0; ks < 8; ++ks) {
            e0 += g_Gp[(size_t)((0 * 4 + t4) * 8 + ks) * 16384 + locv];
            z0 += g_Gp[(size_t)((2 * 4 + t4) * 8 + ks) * 16384 + locv];
            e1 += g_Gp[(size_t)((1 * 4 + t4) * 8 + ks) * 16384 + locv];
            z1 += g_Gp[(size_t)((3 * 4 + t4) * 8 + ks) * 16384 + locv];
        }
        p0 += e0 * z0;
        p1 += e1 * z1;
    }
    p0 = wsum(p0); p1 = wsum(p1);
    if ((threadIdx.x & 31) == 0) {
        atomicAdd(&g_Sdot[0], p0);
        atomicAdd(&g_Sdot[1], p1);
    }
}

// ---------------- 9. S finalize ----------------
__global__ void k_sfin(float* __restrict__ out) {
    __shared__ float red[12][8];
    int tid = threadIdx.x, lane = tid & 31, w = tid >> 5;
    float p[12];
#pragma unroll
    for (int i = 0; i < 12; ++i) p[i] = 0.f;
    for (int n = tid; n < NPOS; n += 256) {
        float ak = g_akd[n], ag = g_agan[n];
        float bk = g_bkd[n], bg = g_bgan[n];
        p[0] += ak; p[1] += ak * ak;
        p[2] += ag; p[3] += ag * ag;
        p[4] += bk; p[5] += bk * bk;
        p[6] += bg; p[7] += bg * bg;
    }
    {
        int c = tid;
        p[8]  += g_vec[1536 + c] * g_vec[c];
        p[10] += g_vec[1024 + c] * g_vec[512 + c];
        int c2 = tid + 256;
        p[9]  += g_vec[1536 + c2] * g_vec[c2];
        p[11] += g_vec[1024 + c2] * g_vec[512 + c2];
    }
#pragma unroll
    for (int i = 0; i < 12; ++i) {
        float v = wsum(p[i]);
        if (lane == 0) red[i][w] = v;
    }
    __syncthreads();
    if (tid == 0) {
        double tt[12];
#pragma unroll
        for (int i = 0; i < 12; ++i) {
            double s = 0.0;
            for (int j = 0; j < 8; ++j) s += (double)red[i][j];
            tt[i] = s;
        }
        double N = 8192.0;
        double Skd = (N * tt[1] + 2.0 * tt[0] * tt[4] + N * tt[5]
                      - 4.0 * tt[8] - 4.0 * tt[10] + 4.0 * (double)g_Sdot[0]) / N;
        double Sgn = (N * tt[3] + 2.0 * tt[2] * tt[6] + N * tt[7]
                      - 4.0 * tt[9] - 4.0 * tt[11] + 4.0 * (double)g_Sdot[1]) / N;
        out[NQ]     = (float)Skd;
        out[NQ + 1] = (float)Sgn;
    }
}

// ---------------- 10. z_q gather (tiled, coalesced) ----------------
__global__ void k_zq(float* __restrict__ out) {
    __shared__ float sm[64][133];
    __shared__ int sidx[64];
    int n0 = blockIdx.x * 64;
    int b = n0 >> 10, l0 = n0 & 1023;
    int t = threadIdx.x;
    if (t < 64) sidx[t] = g_idx[n0 + t];
    __syncthreads();
    int w = t >> 5, lane = t & 31;
    int dl0 = t >> 6, nn2 = t & 63;
#pragma unroll 1
    for (int dc = 0; dc < 4; ++dc) {
        int d0 = dc * 128;
#pragma unroll
        for (int i = 0; i < 8; ++i) {
            int nn = w * 8 + i;
            float4 v = ((const float4*)(g_En + (size_t)sidx[nn] * EDIM + d0))[lane];
            sm[nn][lane * 4 + 0] = v.x;
            sm[nn][lane * 4 + 1] = v.y;
            sm[nn][lane * 4 + 2] = v.z;
            sm[nn][lane * 4 + 3] = v.w;
        }
        __syncthreads();
#pragma unroll 8
        for (int pp = 0; pp < 128; pp += 4) {
            int d = d0 + pp + dl0;
            float zn = g_ZnT[(size_t)d * NPOS + n0 + nn2];
            float ev = sm[nn2][pp + dl0];
            out[((size_t)(b * D_ + d)) * L_ + l0 + nn2] = zn + (ev - zn);
        }
        __syncthreads();
    }
}

extern "C" void kernel_launch(void* const* d_in, const int* in_sizes, int n_in,
                              void* d_out, int out_size) {
    (void)in_sizes; (void)n_in; (void)out_size;
    const float* z    = (const float*)d_in[0];
    const float* ekd  = (const float*)d_in[1];
    const float* egan = (const float*)d_in[2];
    float* out = (float*)d_out;

    static int inited = 0;
    if (!inited) {
        cudaFuncSetAttribute(k_gemm_mma, cudaFuncAttributeMaxDynamicSharedMemorySize, 4 * STG4);
        cudaFuncSetAttribute(k_gram,     cudaFuncAttributeMaxDynamicSharedMemorySize, 4 * STG4);
        inited = 1;
    }

    k_prep<<<1024 + 256, 256>>>(z, ekd, egan);
    k_zfinal<<<NPOS / 256, 256>>>();
    k_ztrans<<<dim3(16, 32, 8), dim3(32, 8)>>>(z);
    k_gemm_mma<<<4096, 256, 4 * STG4>>>();
    k_gram<<<128, 256, 4 * STG4>>>();
    k_colsum<<<256, 256>>>();
    k_scan<<<NPOS / 8, 256>>>(out);
    k_sdot<<<64, 256>>>();
    k_sfin<<<1, 256>>>(out);
    k_zq<<<128, 256>>>(out);
}

// round 13
// speedup vs baseline: 1.9194x; 1.1865x over previous
#include <cuda_runtime.h>
#include <cuda_bf16.h>
#include <cuda_fp16.h>
#include <math.h>
#include <stdint.h>

#define B_    8
#define D_    512
#define L_    1024
#define NPOS  8192
#define KCB   8192
#define EDIM  512
#define SEMD  256
#define NQ    4194304

typedef unsigned long long ull;

// ---------------- scratch ----------------
static __device__ float g_Zn [NPOS * EDIM];
static __device__ float g_ZnT[EDIM * NPOS];
static __device__ char  g_ZnQ[NPOS * EDIM];
static __device__ float g_En [KCB * EDIM];
static __device__ char  g_EnQ[KCB * EDIM];
static __device__ __nv_bfloat16 g_ETb[EDIM * KCB];
static __device__ __nv_bfloat16 g_ZTb[EDIM * NPOS];
static __device__ float g_psum[8][NPOS];
static __device__ float g_pmax[8][NPOS];
static __device__ float g_invk[NPOS], g_invg[NPOS];
static __device__ float g_akd[NPOS],  g_agan[NPOS];
static __device__ float g_bkd[KCB],   g_bgan[KCB];
static __device__ float g_a[NPOS], g_b[KCB];
static __device__ float g_sZ[NPOS], g_sE[KCB];
static __device__ __half g_Dh[(size_t)NPOS * KCB];
static __device__ unsigned g_keyu[NPOS];
static __device__ int   g_idx[NPOS];
static __device__ float g_Gp[128 * 16384];
static __device__ float g_vec[2048];
static __device__ float g_Sdot[2];

// ---------------- helpers ----------------
__device__ __forceinline__ float wsum(float s) {
#pragma unroll
    for (int o = 16; o > 0; o >>= 1) s += __shfl_xor_sync(0xffffffffu, s, o);
    return s;
}
__device__ __forceinline__ float wmax(float s) {
#pragma unroll
    for (int o = 16; o > 0; o >>= 1) s = fmaxf(s, __shfl_xor_sync(0xffffffffu, s, o));
    return s;
}
__device__ __forceinline__ unsigned s2u(const void* p) {
    unsigned a;
    asm("{ .reg .u64 t; cvta.to.shared.u64 t, %1; cvt.u32.u64 %0, t; }" : "=r"(a) : "l"(p));
    return a;
}
__device__ __forceinline__ void cpasync16(unsigned s, const void* g) {
    asm volatile("cp.async.cg.shared.global [%0], [%1], 16;\n" :: "r"(s), "l"(g));
}
__device__ __forceinline__ void ldsm4(unsigned addr, unsigned &r0, unsigned &r1,
                                      unsigned &r2, unsigned &r3) {
    asm volatile("ldmatrix.sync.aligned.m8n8.x4.shared.b16 {%0,%1,%2,%3}, [%4];"
                 : "=r"(r0), "=r"(r1), "=r"(r2), "=r"(r3) : "r"(addr));
}
__device__ __forceinline__ void mma_s8(int* c, unsigned a0, unsigned a1, unsigned a2,
                                       unsigned a3, unsigned b0, unsigned b1) {
    asm volatile("mma.sync.aligned.m16n8k32.row.col.s32.s8.s8.s32 "
                 "{%0,%1,%2,%3}, {%4,%5,%6,%7}, {%8,%9}, {%0,%1,%2,%3};"
                 : "+r"(c[0]), "+r"(c[1]), "+r"(c[2]), "+r"(c[3])
                 : "r"(a0), "r"(a1), "r"(a2), "r"(a3), "r"(b0), "r"(b1));
}
__device__ __forceinline__ void mma_bf16(float* c, unsigned a0, unsigned a1, unsigned a2,
                                         unsigned a3, unsigned b0, unsigned b1) {
    asm volatile("mma.sync.aligned.m16n8k16.row.col.f32.bf16.bf16.f32 "
                 "{%0,%1,%2,%3}, {%4,%5,%6,%7}, {%8,%9}, {%0,%1,%2,%3};"
                 : "+f"(c[0]), "+f"(c[1]), "+f"(c[2]), "+f"(c[3])
                 : "r"(a0), "r"(a1), "r"(a2), "r"(a3), "r"(b0), "r"(b1));
}

// ---------------- 1. prep ----------------
__global__ void k_prep(const float* __restrict__ z, const float* __restrict__ ekd,
                       const float* __restrict__ egan) {
    int bid = blockIdx.x;
    if (bid < 1024) {
        __shared__ __nv_bfloat16 smE[EDIM * 8];
        int w = threadIdx.x >> 5, lane = threadIdx.x & 31;
        int k = bid * 8 + w;
        const float* pk = ekd + (size_t)k * SEMD;
        const float* pg = egan + (size_t)k * SEMD;
        float v[8], u[8]; float sk = 0.f, sg = 0.f;
#pragma unroll
        for (int j = 0; j < 8; ++j) {
            v[j] = pk[lane + j * 32]; sk += v[j] * v[j];
            u[j] = pg[lane + j * 32]; sg += u[j] * u[j];
        }
        sk = wsum(sk); sg = wsum(sg);
        float ik = 1.f / fmaxf(sqrtf(sk), 1e-12f);
        float ig = 1.f / fmaxf(sqrtf(sg), 1e-12f);
        float m = 0.f, tk = 0.f, tg = 0.f;
#pragma unroll
        for (int j = 0; j < 8; ++j) {
            v[j] *= ik; u[j] *= ig;
            m = fmaxf(m, fmaxf(fabsf(v[j]), fabsf(u[j])));
            tk += v[j] * v[j]; tg += u[j] * u[j];
        }
        m = wmax(m); tk = wsum(tk); tg = wsum(tg);
        float qs = 127.f / fmaxf(m, 1e-20f);
#pragma unroll
        for (int j = 0; j < 8; ++j) {
            int e1 = lane + j * 32;
            size_t o = (size_t)k * EDIM + e1;
            g_En[o] = v[j];          g_EnQ[o] = (char)__float2int_rn(v[j] * qs);
            g_En[o + SEMD] = u[j];   g_EnQ[o + SEMD] = (char)__float2int_rn(u[j] * qs);
            smE[e1 * 8 + w] = __float2bfloat16_rn(v[j]);
            smE[(e1 + SEMD) * 8 + w] = __float2bfloat16_rn(u[j]);
        }
        if (lane == 0) {
            g_bkd[k] = tk; g_bgan[k] = tg;
            g_b[k] = tk + tg;
            g_sE[k] = m * (1.f / 127.f);
        }
        __syncthreads();
        int t = threadIdx.x, k0 = bid * 8;
#pragma unroll
        for (int rr = 0; rr < 2; ++rr) {
            int e = t * 2 + rr;
            *(uint4*)(g_ETb + (size_t)e * KCB + k0) = *(const uint4*)&smE[e * 8];
        }
    } else {
        int i = bid - 1024;
        int l = (i & 3) * 256 + threadIdx.x;
        int b = (i >> 2) & 7, seg = i >> 5;
        const float* p = z + (size_t)b * D_ * L_ + (size_t)seg * 64 * L_ + l;
        float s = 0.f, m = 0.f;
#pragma unroll 8
        for (int d = 0; d < 64; ++d) {
            float v = p[(size_t)d * L_];
            s += v * v; m = fmaxf(m, fabsf(v));
        }
        g_psum[seg][b * L_ + l] = s;
        g_pmax[seg][b * L_ + l] = m;
    }
}

// ---------------- 2. finalize norms/scales ----------------
__global__ void k_zfinal() {
    int n = blockIdx.x * 256 + threadIdx.x;
    float s = g_psum[0][n] + g_psum[1][n] + g_psum[2][n] + g_psum[3][n];
    float inv = 1.f / fmaxf(sqrtf(s), 1e-12f);
    g_invk[n] = inv;
    float akd = s * inv * inv; g_akd[n] = akd;
    float mk = fmaxf(fmaxf(g_pmax[0][n], g_pmax[1][n]), fmaxf(g_pmax[2][n], g_pmax[3][n])) * inv;
    float s2 = g_psum[4][n] + g_psum[5][n] + g_psum[6][n] + g_psum[7][n];
    float inv2 = 1.f / fmaxf(sqrtf(s2), 1e-12f);
    g_invg[n] = inv2;
    float agan = s2 * inv2 * inv2; g_agan[n] = agan;
    float mg = fmaxf(fmaxf(g_pmax[4][n], g_pmax[5][n]), fmaxf(g_pmax[6][n], g_pmax[7][n])) * inv2;
    g_a[n] = akd + agan;
    g_sZ[n] = fmaxf(mk, mg) * (1.f / 127.f);
    g_keyu[n] = 0xFFFFFFFFu;
    if (n < 2048) g_vec[n] = 0.f;
    if (n < 2) g_Sdot[n] = 0.f;
}

// ---------------- 3. transpose + normalize + quantize z ----------------
__global__ void k_ztrans(const float* __restrict__ z) {
    __shared__ float s[32][33];
    __shared__ float invA[32], rqA[32];
    int d0 = blockIdx.x * 32, l0 = blockIdx.y * 32, b = blockIdx.z;
    int tx = threadIdx.x, ty = threadIdx.y;
    int n0 = b * L_ + l0;
    bool kdh = (d0 < SEMD);
    if (ty == 0) invA[tx] = kdh ? g_invk[n0 + tx] : g_invg[n0 + tx];
    if (ty == 1) rqA[tx] = 1.f / g_sZ[n0 + tx];
#pragma unroll
    for (int q = 0; q < 4; ++q) {
        int dy = ty * 4 + q;
        s[dy][tx] = z[((size_t)b * D_ + d0 + dy) * L_ + l0 + tx];
    }
    __syncthreads();
#pragma unroll
    for (int q = 0; q < 4; ++q) {
        int lr = ty * 4 + q;
        int n = n0 + lr;
        float v = s[tx][lr] * invA[lr];
        size_t o = (size_t)n * EDIM + d0 + tx;
        g_Zn[o] = v;
        g_ZnQ[o] = (char)__float2int_rn(v * rqA[lr]);
    }
#pragma unroll
    for (int q = 0; q < 4; ++q) {
        int dy = ty * 4 + q;
        float v = s[dy][tx] * invA[tx];
        size_t o = (size_t)(d0 + dy) * NPOS + n0 + tx;
        g_ZnT[o] = v;
        g_ZTb[o] = __float2bfloat16_rn(v);
    }
}

// ---------------- 4. int8 mma GEMM 128x128, chunk=128, 3-stage, 2 CTAs/SM ----------------
// stage = A(128*144) + B(128*144) = 36864B; 3 stages = 110592B
#define STG3 36864
__global__ void __launch_bounds__(256, 2) k_gemm_mma() {
    extern __shared__ char dsm[];

    const int tid = threadIdx.x, lane = tid & 31, w = tid >> 5;
    const int bid = blockIdx.x;
    const int sup = bid >> 8, loc = bid & 255;
    const int kt = ((sup & 3) << 4) | (loc & 15);
    const int rt = ((sup >> 2) << 4) | (loc >> 4);
    const int row0 = rt * 128, k0 = kt * 128;
    const int wm = w & 3, wn = w >> 2;

    unsigned sbase = s2u(dsm);

    auto load_chunk = [&](int c) {
        int st = c % 3;
        int e0 = c * 128;
        const char* Ag = g_ZnQ + (size_t)row0 * EDIM + e0;
        const char* Bg = g_EnQ + (size_t)k0 * EDIM + e0;
        unsigned ab = sbase + st * STG3;
        unsigned bb = ab + 18432;
#pragma unroll
        for (int i = 0; i < 4; ++i) {
            int q = tid + i * 256; int r = q >> 3, ch = q & 7;
            cpasync16(ab + r * 144 + ch * 16, Ag + (size_t)r * EDIM + ch * 16);
        }
#pragma unroll
        for (int i = 0; i < 4; ++i) {
            int q = tid + i * 256; int r = q >> 3, ch = q & 7;
            cpasync16(bb + r * 144 + ch * 16, Bg + (size_t)r * EDIM + ch * 16);
        }
        asm volatile("cp.async.commit_group;" ::: "memory");
    };

    int acc[2][8][4];
#pragma unroll
    for (int t = 0; t < 2; ++t)
#pragma unroll
        for (int j = 0; j < 8; ++j)
#pragma unroll
            for (int q = 0; q < 4; ++q) acc[t][j][q] = 0;

    const int lr = lane & 7, lg = lane >> 3;

    auto compute = [&](int st) {
        unsigned ab = sbase + st * STG3;
        unsigned bb = ab + 18432;
#pragma unroll
        for (int s = 0; s < 4; ++s) {               // four k32 steps per 128-int8 chunk
            unsigned a0[2], a1[2], a2[2], a3[2];
#pragma unroll
            for (int t = 0; t < 2; ++t) {
                int row = wm * 32 + t * 16 + lr + 8 * (lg & 1);
                ldsm4(ab + row * 144 + s * 32 + 16 * (lg >> 1), a0[t], a1[t], a2[t], a3[t]);
            }
            unsigned bf[8][2];
#pragma unroll
            for (int jp = 0; jp < 4; ++jp) {
                int brow = wn * 64 + (jp * 2 + (lg >> 1)) * 8 + lr;
                ldsm4(bb + brow * 144 + s * 32 + 16 * (lg & 1),
                      bf[jp * 2][0], bf[jp * 2][1], bf[jp * 2 + 1][0], bf[jp * 2 + 1][1]);
            }
#pragma unroll
            for (int t = 0; t < 2; ++t)
#pragma unroll
                for (int j = 0; j < 8; ++j)
                    mma_s8(acc[t][j], a0[t], a1[t], a2[t], a3[t], bf[j][0], bf[j][1]);
        }
    };

    load_chunk(0); load_chunk(1); load_chunk(2);
    asm volatile("cp.async.wait_group 2;" ::: "memory");
    __syncthreads();
    compute(0);
    __syncthreads();                 // stage 0 fully consumed by all warps
    load_chunk(3);
    asm volatile("cp.async.wait_group 2;" ::: "memory");
    __syncthreads();
    compute(1);
    asm volatile("cp.async.wait_group 1;" ::: "memory");
    __syncthreads();
    compute(2);
    asm volatile("cp.async.wait_group 0;" ::: "memory");
    __syncthreads();
    compute(0);                      // chunk 3 lives in stage 0

    // ---- epilogue ----
    const int lq = lane >> 2, lp = lane & 3;
    const int kb = k0 + wn * 64 + lp * 2;
#pragma unroll
    for (int t = 0; t < 2; ++t) {
        int rA = row0 + wm * 32 + t * 16 + lq;
#pragma unroll
        for (int h = 0; h < 2; ++h) {
            int rr = rA + 8 * h;
            float a_ = g_a[rr];
            float tz = 2.f * g_sZ[rr];
            unsigned rmin = 0xFFFFFFFFu;
            __half* drow = g_Dh + (size_t)rr * KCB;
#pragma unroll
            for (int j = 0; j < 8; ++j) {
                int kk = kb + j * 8;
                float d0 = (a_ + g_b[kk])     - tz * g_sE[kk]     * (float)acc[t][j][2 * h];
                float d1 = (a_ + g_b[kk + 1]) - tz * g_sE[kk + 1] * (float)acc[t][j][2 * h + 1];
                rmin = min(rmin, min(__float_as_uint(d0), __float_as_uint(d1)));
                *(__half2*)(drow + kk) = __floats2half2_rn(d0, d1);
            }
            rmin = min(rmin, __shfl_xor_sync(0xffffffffu, rmin, 1));
            rmin = min(rmin, __shfl_xor_sync(0xffffffffu, rmin, 2));
            if (lp == 0) atomicMin(&g_keyu[rr], rmin);
        }
    }
}

// ---------------- 5. Grams via bf16 mma, k-split 8, plain stores ----------------
#define STG4 20480
__global__ void __launch_bounds__(256, 2) k_gram() {
    extern __shared__ char gsm[];
    const int tid = threadIdx.x, lane = tid & 31, w = tid >> 5;
    const int x = blockIdx.x;
    const int jt = x & 1, it = (x >> 1) & 1;
    const int job = (x >> 2) & 3;
    const int ks = x >> 4;
    const __nv_bfloat16* Mp = (job < 2) ? g_ETb : g_ZTb;
    const int rowbase = (job & 1) * 256;
    const __nv_bfloat16* Abase_ = Mp + (size_t)(rowbase + it * 128) * KCB;
    const __nv_bfloat16* Bbase_ = Mp + (size_t)(rowbase + jt * 128) * KCB;
    const int n00 = ks * 1024;
    const int wm = w & 3, wn = w >> 2;

    unsigned sbase = s2u(gsm);

    auto load_chunk = [&](int c) {
        int st = c & 3;
        int off = n00 + c * 32;
        unsigned ab = sbase + st * STG4;
        unsigned bb = ab + 10240;
#pragma unroll
        for (int i = 0; i < 2; ++i) {
            int q = tid + i * 256; int r = q >> 2, ch = q & 3;
            cpasync16(ab + r * 80 + ch * 16, Abase_ + (size_t)r * KCB + off + ch * 8);
        }
#pragma unroll
        for (int i = 0; i < 2; ++i) {
            int q = tid + i * 256; int r = q >> 2, ch = q & 3;
            cpasync16(bb + r * 80 + ch * 16, Bbase_ + (size_t)r * KCB + off + ch * 8);
        }
        asm volatile("cp.async.commit_group;" ::: "memory");
    };

    float acc[2][8][4];
#pragma unroll
    for (int t = 0; t < 2; ++t)
#pragma unroll
        for (int j = 0; j < 8; ++j)
#pragma unroll
            for (int q = 0; q < 4; ++q) acc[t][j][q] = 0.f;

    const int lr = lane & 7, lg = lane >> 3;

    auto compute = [&](int st) {
        unsigned ab = sbase + st * STG4;
        unsigned bb = ab + 10240;
#pragma unroll
        for (int s = 0; s < 2; ++s) {
            unsigned a0[2], a1[2], a2[2], a3[2];
#pragma unroll
            for (int t = 0; t < 2; ++t) {
                int row = wm * 32 + t * 16 + lr + 8 * (lg & 1);
                int col = s * 16 + 8 * (lg >> 1);
                ldsm4(ab + row * 80 + col * 2, a0[t], a1[t], a2[t], a3[t]);
            }
            unsigned bf[8][2];
#pragma unroll
            for (int jp = 0; jp < 4; ++jp) {
                int brow = wn * 64 + (jp * 2 + (lg >> 1)) * 8 + lr;
                int bcol = s * 16 + 8 * (lg & 1);
                ldsm4(bb + brow * 80 + bcol * 2,
                      bf[jp * 2][0], bf[jp * 2][1], bf[jp * 2 + 1][0], bf[jp * 2 + 1][1]);
            }
#pragma unroll
            for (int t = 0; t < 2; ++t)
#pragma unroll
                for (int j = 0; j < 8; ++j)
                    mma_bf16(acc[t][j], a0[t], a1[t], a2[t], a3[t], bf[j][0], bf[j][1]);
        }
    };

    load_chunk(0); load_chunk(1); load_chunk(2);
#pragma unroll 1
    for (int c = 0; c < 32; ++c) {
        asm volatile("cp.async.wait_group 2;" ::: "memory");
        __syncthreads();
        if (c + 3 < 32) load_chunk(c + 3);
        compute(c & 3);
    }

    float* Gp = g_Gp + (size_t)(((job * 4 + it * 2 + jt) * 8) + ks) * 16384;
    const int lq = lane >> 2, lp = lane & 3;
    const int jb = wn * 64 + lp * 2;
#pragma unroll
    for (int t = 0; t < 2; ++t) {
        int rA = wm * 32 + t * 16 + lq;
#pragma unroll
        for (int h = 0; h < 2; ++h) {
            int rr = rA + 8 * h;
#pragma unroll
            for (int j = 0; j < 8; ++j) {
                int kk = jb + j * 8;
                *(float2*)&Gp[rr * 128 + kk] =
                    make_float2(acc[t][j][2 * h], acc[t][j][2 * h + 1]);
            }
        }
    }
}

// ---------------- 6. column sums ----------------
__global__ void k_colsum() {
    int job = blockIdx.x >> 7;
    int r0 = (blockIdx.x & 127) * 64;
    const float* M = job ? g_Zn : g_En;
    const float* betak = job ? g_akd : g_bkd;
    const float* betag = job ? g_agan : g_bgan;
    int t = threadIdx.x;
    float s1a = 0.f, s2a = 0.f, s1b = 0.f, s2b = 0.f;
    for (int r = r0; r < r0 + 64; ++r) {
        float bk = betak[r], bg = betag[r];
        float x1 = M[(size_t)r * EDIM + t];
        float x2 = M[(size_t)r * EDIM + t + 256];
        s1a += x1; s2a += bk * x1;
        s1b += x2; s2b += bg * x2;
    }
    atomicAdd(&g_vec[job * 1024 + t],       s1a);
    atomicAdd(&g_vec[job * 1024 + 512 + t], s2a);
    atomicAdd(&g_vec[job * 1024 + 256 + t],       s1b);
    atomicAdd(&g_vec[job * 1024 + 512 + 256 + t], s2b);
}

// ---------------- 7. scan + warp-cooperative exact rescore ----------------
__global__ void k_scan(float* __restrict__ out) {
    __shared__ int scnt[8];
    __shared__ int slist[8][96];
    int w = threadIdx.x >> 5, lane = threadIdx.x & 31;
    int n = blockIdx.x * 8 + w;
    if (lane == 0) scnt[w] = 0;
    __syncwarp();
    float th = __uint_as_float(g_keyu[n]) + 6.5e-2f;
    const __half2* row = (const __half2*)(g_Dh + (size_t)n * KCB);
#pragma unroll 8
    for (int i = 0; i < 128; ++i) {
        int p = i * 32 + lane;
        float2 fv = __half22float2(row[p]);
        if (fv.x <= th) { int s = atomicAdd(&scnt[w], 1); if (s < 96) slist[w][s] = p * 2; }
        if (fv.y <= th) { int s = atomicAdd(&scnt[w], 1); if (s < 96) slist[w][s] = p * 2 + 1; }
    }
    __syncwarp();
    int nc = min(scnt[w], 96);
    const float* zr = g_Zn + (size_t)n * EDIM;
    float4 zv[4];
#pragma unroll
    for (int q = 0; q < 4; ++q) zv[q] = *(const float4*)(zr + lane * 4 + q * 128);
    float akd = g_akd[n], agn = g_agan[n];
    ull bkey = ~0ull;
    for (int c2 = 0; c2 < nc; ++c2) {
        int k = slist[w][c2];
        const float* er = g_En + (size_t)k * EDIM;
        float ck = 0.f, cg = 0.f;
#pragma unroll
        for (int q = 0; q < 4; ++q) {
            float4 ev = *(const float4*)(er + lane * 4 + q * 128);
            float dd = zv[q].x * ev.x + zv[q].y * ev.y + zv[q].z * ev.z + zv[q].w * ev.w;
            if (q < 2) ck += dd; else cg += dd;
        }
        ck = wsum(ck); cg = wsum(cg);
        float d = ((akd + g_bkd[k]) - 2.f * ck) + ((agn + g_bgan[k]) - 2.f * cg);
        ull key = ((ull)__float_as_uint(d) << 32) | (unsigned)k;
        if (key < bkey) bkey = key;
    }
    if (lane == 0) {
        int bi = (int)(unsigned)bkey;
        g_idx[n] = bi;
        out[NQ + 2 + n] = (float)bi;
    }
}

// ---------------- 8. <G_E, G_Z> from partials ----------------
__global__ void k_sdot() {
    int idx = blockIdx.x * 256 + threadIdx.x;
    float p0 = 0.f, p1 = 0.f;
    for (int i = idx; i < 65536; i += 16384) {
        int t4 = i >> 14, locv = i & 16383;
        float e0 = 0.f, z0 = 0.f, e1 = 0.f, z1 = 0.f;
#pragma unroll
        for (int ks = 0; ks < 8; ++ks) {
            e0 += g_Gp[(size_t)((0 * 4 + t4) * 8 + ks) * 16384 + locv];
            z0 += g_Gp[(size_t)((2 * 4 + t4) * 8 + ks) * 16384 + locv];
            e1 += g_Gp[(size_t)((1 * 4 + t4) * 8 + ks) * 16384 + locv];
            z1 += g_Gp[(size_t)((3 * 4 + t4) * 8 + ks) * 16384 + locv];
        }
        p0 += e0 * z0;
        p1 += e1 * z1;
    }
    p0 = wsum(p0); p1 = wsum(p1);
    if ((threadIdx.x & 31) == 0) {
        atomicAdd(&g_Sdot[0], p0);
        atomicAdd(&g_Sdot[1], p1);
    }
}

// ---------------- 9. S finalize ----------------
__global__ void k_sfin(float* __restrict__ out) {
    __shared__ float red[12][8];
    int tid = threadIdx.x, lane = tid & 31, w = tid >> 5;
    float p[12];
#pragma unroll
    for (int i = 0; i < 12; ++i) p[i] = 0.f;
    for (int n = tid; n < NPOS; n += 256) {
        float ak = g_akd[n], ag = g_agan[n];
        float bk = g_bkd[n], bg = g_bgan[n];
        p[0] += ak; p[1] += ak * ak;
        p[2] += ag; p[3] += ag * ag;
        p[4] += bk; p[5] += bk * bk;
        p[6] += bg; p[7] += bg * bg;
    }
    {
        int c = tid;
        p[8]  += g_vec[1536 + c] * g_vec[c];
        p[10] += g_vec[1024 + c] * g_vec[512 + c];
        int c2 = tid + 256;
        p[9]  += g_vec[1536 + c2] * g_vec[c2];
        p[11] += g_vec[1024 + c2] * g_vec[512 + c2];
    }
#pragma unroll
    for (int i = 0; i < 12; ++i) {
        float v = wsum(p[i]);
        if (lane == 0) red[i][w] = v;
    }
    __syncthreads();
    if (tid == 0) {
        double tt[12];
#pragma unroll
        for (int i = 0; i < 12; ++i) {
            double s = 0.0;
            for (int j = 0; j < 8; ++j) s += (double)red[i][j];
            tt[i] = s;
        }
        double N = 8192.0;
        double Skd = (N * tt[1] + 2.0 * tt[0] * tt[4] + N * tt[5]
                      - 4.0 * tt[8] - 4.0 * tt[10] + 4.0 * (double)g_Sdot[0]) / N;
        double Sgn = (N * tt[3] + 2.0 * tt[2] * tt[6] + N * tt[7]
                      - 4.0 * tt[9] - 4.0 * tt[11] + 4.0 * (double)g_Sdot[1]) / N;
        out[NQ]     = (float)Skd;
        out[NQ + 1] = (float)Sgn;
    }
}

// ---------------- 10. z_q gather ----------------
__global__ void k_zq(float* __restrict__ out) {
    __shared__ float sm[64][133];
    __shared__ int sidx[64];
    int n0 = blockIdx.x * 64;
    int b = n0 >> 10, l0 = n0 & 1023;
    int t = threadIdx.x;
    if (t < 64) sidx[t] = g_idx[n0 + t];
    __syncthreads();
    int w = t >> 5, lane = t & 31;
    int dl0 = t >> 6, nn2 = t & 63;
#pragma unroll 1
    for (int dc = 0; dc < 4; ++dc) {
        int d0 = dc * 128;
#pragma unroll
        for (int i = 0; i < 8; ++i) {
            int nn = w * 8 + i;
            float4 v = ((const float4*)(g_En + (size_t)sidx[nn] * EDIM + d0))[lane];
            sm[nn][lane * 4 + 0] = v.x;
            sm[nn][lane * 4 + 1] = v.y;
            sm[nn][lane * 4 + 2] = v.z;
            sm[nn][lane * 4 + 3] = v.w;
        }
        __syncthreads();
#pragma unroll 8
        for (int pp = 0; pp < 128; pp += 4) {
            int d = d0 + pp + dl0;
            float zn = g_ZnT[(size_t)d * NPOS + n0 + nn2];
            float ev = sm[nn2][pp + dl0];
            out[((size_t)(b * D_ + d)) * L_ + l0 + nn2] = zn + (ev - zn);
        }
        __syncthreads();
    }
}

extern "C" void kernel_launch(void* const* d_in, const int* in_sizes, int n_in,
                              void* d_out, int out_size) {
    (void)in_sizes; (void)n_in; (void)out_size;
    const float* z    = (const float*)d_in[0];
    const float* ekd  = (const float*)d_in[1];
    const float* egan = (const float*)d_in[2];
    float* out = (float*)d_out;

    static int inited = 0;
    static cudaStream_t s2;
    static cudaEvent_t evA, evB;
    if (!inited) {
        cudaFuncSetAttribute(k_gemm_mma, cudaFuncAttributeMaxDynamicSharedMemorySize, 3 * STG3);
        cudaFuncSetAttribute(k_gram,     cudaFuncAttributeMaxDynamicSharedMemorySize, 4 * STG4);
        cudaStreamCreateWithFlags(&s2, cudaStreamNonBlocking);
        cudaEventCreateWithFlags(&evA, cudaEventDisableTiming);
        cudaEventCreateWithFlags(&evB, cudaEventDisableTiming);
        inited = 1;
    }

    k_prep<<<1024 + 256, 256>>>(z, ekd, egan);
    k_zfinal<<<NPOS / 256, 256>>>();
    k_ztrans<<<dim3(16, 32, 8), dim3(32, 8)>>>(z);

    // fork: S-identity branch runs concurrently with the GEMM chain
    cudaEventRecord(evA, 0);
    cudaStreamWaitEvent(s2, evA, 0);
    k_gram<<<128, 256, 4 * STG4, s2>>>();
    k_colsum<<<256, 256, 0, s2>>>();
    k_sdot<<<64, 256, 0, s2>>>();
    k_sfin<<<1, 256, 0, s2>>>(out);
    cudaEventRecord(evB, s2);

    k_gemm_mma<<<4096, 256, 3 * STG3>>>();
    k_scan<<<NPOS / 8, 256>>>(out);
    k_zq<<<128, 256>>>(out);

    // join
    cudaStreamWaitEvent(0, evB, 0);
}